// round 7
// baseline (speedup 1.0000x reference)
#include <cuda_runtime.h>
#include <cuda_bf16.h>
#include <stdint.h>

#define KNS 100000
#define KNT 50000
#define KE  600000
#define KD  128
#define BN_EPS 1e-5f
#define NBLK_G 782     // ceil(KNT/64)
#define NBLK_B 98      // builder blocks (resident)

// ---------------- scratch (static device memory; no allocations) ----------------
__device__ float g_h[KNT * KD];
__device__ float g_y1[KNT * KD];
__device__ int   g_counts[KNT];
__device__ int   g_offsets[KNT + 1];
__device__ int   g_cursor[KNT];
__device__ int   g_srcs[KE];
__device__ float g_psum[NBLK_G * KD];
__device__ float g_psq[NBLK_G * KD];
__device__ float g_scale[2 * KD];
__device__ float g_shift[2 * KD];
__device__ int   g_bsum[128];
__device__ unsigned g_bar;
__device__ __align__(16) __nv_bfloat16 g_Wh[2 * KD * KD];
__device__ __align__(16) __nv_bfloat16 g_Wl[2 * KD * KD];

// ---------------- device-wide barrier (all NBLK_B blocks resident) ----------------
__device__ __forceinline__ void gridbar(unsigned target) {
  __syncthreads();
  if (threadIdx.x == 0) {
    __threadfence();
    atomicAdd(&g_bar, 1u);
    while (*((volatile unsigned*)&g_bar) < target) {}
  }
  __syncthreads();
}

// ---------------- precompute hi/lo bf16 split of weights; reset barrier ----------
__global__ void splitw_kernel(const float* __restrict__ W1,
                              const float* __restrict__ W2) {
  int i = blockIdx.x * 256 + threadIdx.x;  // 0..8191, 4 elems each
  if (i == 0) g_bar = 0;
  if (i >= 8192) return;
  const float* W = (i < 4096) ? W1 : W2;
  int local = (i < 4096) ? i : (i - 4096);
  float4 v = *reinterpret_cast<const float4*>(W + local * 4);
  float arr[4] = {v.x, v.y, v.z, v.w};
  int o = i * 4;
#pragma unroll
  for (int j = 0; j < 4; j++) {
    __nv_bfloat16 h = __float2bfloat16_rn(arr[j]);
    g_Wh[o + j] = h;
    g_Wl[o + j] = __float2bfloat16_rn(arr[j] - __bfloat162float(h));
  }
}

__device__ __forceinline__ int warp_incl_scan(int x, int lane) {
#pragma unroll
  for (int o = 1; o < 32; o <<= 1) {
    int y = __shfl_up_sync(0xffffffffu, x, o);
    if (lane >= o) x += y;
  }
  return x;
}

// ------- builder: zero + histogram + exclusive scan + scatter in ONE kernel -------
__global__ void build_kernel(const int* __restrict__ src, const int* __restrict__ dst) {
  __shared__ int ws[16];
  __shared__ int sbase;
  int t = threadIdx.x, b = blockIdx.x;
  int i = b * 512 + t;
  int lane = t & 31, w = t >> 5;

  if (i < KNT) g_counts[i] = 0;
  gridbar(NBLK_B);

  const int4* dst4 = reinterpret_cast<const int4*>(dst);
  for (int e = i; e < KE / 4; e += NBLK_B * 512) {
    int4 d = dst4[e];
    atomicAdd(&g_counts[d.x], 1);
    atomicAdd(&g_counts[d.y], 1);
    atomicAdd(&g_counts[d.z], 1);
    atomicAdd(&g_counts[d.w], 1);
  }
  gridbar(2 * NBLK_B);

  int v = (i < KNT) ? __ldcg(&g_counts[i]) : 0;
  int x = warp_incl_scan(v, lane);
  if (lane == 31) ws[w] = x;
  __syncthreads();
  if (t < 16) {
    int y = ws[t];
#pragma unroll
    for (int o = 1; o < 16; o <<= 1) {
      int z = __shfl_up_sync(0xffffu, y, o);
      if (t >= o) y += z;
    }
    ws[t] = y;
  }
  __syncthreads();
  int incl = x + (w > 0 ? ws[w - 1] : 0);
  int ex = incl - v;
  if (t == 511) g_bsum[b] = incl;
  gridbar(3 * NBLK_B);

  int contrib = (t < b) ? __ldcg(&g_bsum[t]) : 0;
#pragma unroll
  for (int o = 16; o; o >>= 1) contrib += __shfl_down_sync(0xffffffffu, contrib, o);
  if (lane == 0) ws[w] = contrib;
  __syncthreads();
  if (t == 0) {
    int s = 0;
#pragma unroll
    for (int j = 0; j < 16; j++) s += ws[j];
    sbase = s;
  }
  __syncthreads();
  int off = ex + sbase;
  if (i < KNT) {
    g_offsets[i] = off;
    g_cursor[i] = off;
  }
  if (b == 0 && t == 0) g_offsets[KNT] = KE;
  gridbar(4 * NBLK_B);

  const int4* src4 = reinterpret_cast<const int4*>(src);
  for (int e = i; e < KE / 4; e += NBLK_B * 512) {
    int4 s = src4[e];
    int4 d = dst4[e];
    g_srcs[atomicAdd(&g_cursor[d.x], 1)] = s.x;
    g_srcs[atomicAdd(&g_cursor[d.y], 1)] = s.y;
    g_srcs[atomicAdd(&g_cursor[d.z], 1)] = s.z;
    g_srcs[atomicAdd(&g_cursor[d.w], 1)] = s.w;
  }
}

// ---------------- aggregation: one warp per target, high occupancy ----------------
__global__ __launch_bounds__(256, 6) void aggregate_kernel(const float* __restrict__ xs,
                                                           const float* __restrict__ xt,
                                                           const float* __restrict__ eps) {
  int gw = (blockIdx.x * blockDim.x + threadIdx.x) >> 5;
  int lane = threadIdx.x & 31;
  if (gw >= KNT) return;
  float sc = 1.0f + eps[0];
  const float4* xs4 = reinterpret_cast<const float4*>(xs);
  float4 a = reinterpret_cast<const float4*>(xt)[(size_t)gw * 32 + lane];
  a.x *= sc; a.y *= sc; a.z *= sc; a.w *= sc;
  float4 a1 = make_float4(0.f, 0.f, 0.f, 0.f);
  float4 a2 = make_float4(0.f, 0.f, 0.f, 0.f);
  float4 a3 = make_float4(0.f, 0.f, 0.f, 0.f);
  int beg = g_offsets[gw], end = g_offsets[gw + 1];
  int i = beg;
  for (; i + 3 < end; i += 4) {
    int s0 = g_srcs[i], s1 = g_srcs[i + 1], s2 = g_srcs[i + 2], s3 = g_srcs[i + 3];
    float4 v0 = xs4[(size_t)s0 * 32 + lane];
    float4 v1 = xs4[(size_t)s1 * 32 + lane];
    float4 v2 = xs4[(size_t)s2 * 32 + lane];
    float4 v3 = xs4[(size_t)s3 * 32 + lane];
    a.x += v0.x;  a.y += v0.y;  a.z += v0.z;  a.w += v0.w;
    a1.x += v1.x; a1.y += v1.y; a1.z += v1.z; a1.w += v1.w;
    a2.x += v2.x; a2.y += v2.y; a2.z += v2.z; a2.w += v2.w;
    a3.x += v3.x; a3.y += v3.y; a3.z += v3.z; a3.w += v3.w;
  }
  for (; i < end; i++) {
    float4 v0 = xs4[(size_t)g_srcs[i] * 32 + lane];
    a.x += v0.x; a.y += v0.y; a.z += v0.z; a.w += v0.w;
  }
  a.x += a1.x + a2.x + a3.x;
  a.y += a1.y + a2.y + a3.y;
  a.z += a1.z + a2.z + a3.z;
  a.w += a1.w + a2.w + a3.w;
  reinterpret_cast<float4*>(g_h)[(size_t)gw * 32 + lane] = a;
}

// ---------------- GEMM: 32x32 warp tile, pass-scheduled MMAs, hi/lo split ----------
__device__ __forceinline__ void mma_bf16(float* c, const uint32_t* a,
                                         uint32_t b0, uint32_t b1) {
  asm volatile(
      "mma.sync.aligned.m16n8k16.row.col.f32.bf16.bf16.f32 "
      "{%0,%1,%2,%3}, {%4,%5,%6,%7}, {%8,%9}, {%0,%1,%2,%3};\n"
      : "+f"(c[0]), "+f"(c[1]), "+f"(c[2]), "+f"(c[3])
      : "r"(a[0]), "r"(a[1]), "r"(a[2]), "r"(a[3]), "r"(b0), "r"(b1));
}

__device__ __forceinline__ void ldsm4(uint32_t* r, uint32_t addr) {
  asm volatile("ldmatrix.sync.aligned.m8n8.x4.shared.b16 {%0,%1,%2,%3}, [%4];"
               : "=r"(r[0]), "=r"(r[1]), "=r"(r[2]), "=r"(r[3]) : "r"(addr));
}

__device__ __forceinline__ void split2(float x0, float x1, uint32_t& hi, uint32_t& lo) {
  __nv_bfloat162 H = __floats2bfloat162_rn(x0, x1);
  float l0 = x0 - __bfloat162float(H.x);
  float l1 = x1 - __bfloat162float(H.y);
  __nv_bfloat162 L = __floats2bfloat162_rn(l0, l1);
  hi = *reinterpret_cast<uint32_t*>(&H);
  lo = *reinterpret_cast<uint32_t*>(&L);
}

#define WSM_BYTES 32768
template <int LAYER>
__global__ __launch_bounds__(256, 3) void gemm_kernel(const float* __restrict__ bias,
                                                      float* __restrict__ out_param) {
  extern __shared__ char sm[];
  char* WhS = sm;
  float* scaleS = reinterpret_cast<float*>(sm + 2 * WSM_BYTES);  // 128
  float* shiftS = scaleS + 128;                                   // 128
  float* biasS = shiftS + 128;                                    // 128
  float* ssum = biasS + 128;                                      // 2*128
  float* ssq = ssum + 256;                                        // 2*128

  const float* A = (LAYER == 1) ? g_h : g_y1;
  float* out = (LAYER == 1) ? g_y1 : out_param;
  const __nv_bfloat16* GWh = g_Wh + (LAYER - 1) * KD * KD;
  const __nv_bfloat16* GWl = g_Wl + (LAYER - 1) * KD * KD;

  int t = threadIdx.x;
  int row0 = blockIdx.x * 64;
  int w = t >> 5, lane = t & 31;

  if (t < 128) {
    biasS[t] = bias[t];
    if (LAYER == 2) {
      scaleS[t] = g_scale[t];
      shiftS[t] = g_shift[t];
    }
  }
  // stage W hi/lo into swizzled smem: row r, 16B chunk c -> chunk c^(r&7)
  for (int idx = t; idx < 2048; idx += 256) {
    int r = idx >> 4, c = idx & 15;
    int db = r * 256 + ((c ^ (r & 7)) << 4);
    *reinterpret_cast<uint4*>(WhS + db) = reinterpret_cast<const uint4*>(GWh)[idx];
    *reinterpret_cast<uint4*>(WhS + WSM_BYTES + db) = reinterpret_cast<const uint4*>(GWl)[idx];
  }
  __syncthreads();

  int rq = lane >> 2;          // 0..7
  int kq2 = (lane & 3) << 1;   // 0,2,4,6
  int rb = (w >> 2) * 32;      // 2 row groups of 32
  int cb = (w & 3) * 32;       // 4 col groups of 32

  int n_lane = (lane & 7) + ((lane >> 4) << 3);  // 0..15
  int chunk_off = (lane >> 3) & 1;
  int swz7 = n_lane & 7;
  uint32_t whbase = (uint32_t)__cvta_generic_to_shared(WhS);
  uint32_t rowb[2];
#pragma unroll
  for (int p = 0; p < 2; p++) rowb[p] = whbase + (cb + p * 16 + n_lane) * 256;

  int r0 = row0 + rb + rq;   // mt0: rows r0, r0+8
  int r1 = r0 + 16;          // mt1: rows r1, r1+8
  bool ok0 = r0 < KNT, ok1 = (r0 + 8) < KNT, ok2 = r1 < KNT, ok3 = (r1 + 8) < KNT;
  const float* b00 = A + (size_t)(ok0 ? r0 : 0) * 128 + kq2;
  const float* b01 = A + (size_t)(ok1 ? r0 + 8 : 0) * 128 + kq2;
  const float* b10 = A + (size_t)(ok2 ? r1 : 0) * 128 + kq2;
  const float* b11 = A + (size_t)(ok3 ? r1 + 8 : 0) * 128 + kq2;

  float acc[8][4];  // [mt*4 + p*2 + j][..]
#pragma unroll
  for (int i = 0; i < 8; i++)
#pragma unroll
    for (int j = 0; j < 4; j++) acc[i][j] = 0.f;

#pragma unroll
  for (int kk = 0; kk < 128; kk += 16) {
    float2 f0 = *reinterpret_cast<const float2*>(b00 + kk);
    float2 f1 = *reinterpret_cast<const float2*>(b01 + kk);
    float2 f2 = *reinterpret_cast<const float2*>(b00 + kk + 8);
    float2 f3 = *reinterpret_cast<const float2*>(b01 + kk + 8);
    float2 f4 = *reinterpret_cast<const float2*>(b10 + kk);
    float2 f5 = *reinterpret_cast<const float2*>(b11 + kk);
    float2 f6 = *reinterpret_cast<const float2*>(b10 + kk + 8);
    float2 f7 = *reinterpret_cast<const float2*>(b11 + kk + 8);
    if (LAYER == 2) {
      float2 sA = *reinterpret_cast<const float2*>(&scaleS[kk + kq2]);
      float2 hA = *reinterpret_cast<const float2*>(&shiftS[kk + kq2]);
      float2 sB = *reinterpret_cast<const float2*>(&scaleS[kk + kq2 + 8]);
      float2 hB = *reinterpret_cast<const float2*>(&shiftS[kk + kq2 + 8]);
      f0.x = fmaxf(fmaf(sA.x, f0.x, hA.x), 0.f); f0.y = fmaxf(fmaf(sA.y, f0.y, hA.y), 0.f);
      f1.x = fmaxf(fmaf(sA.x, f1.x, hA.x), 0.f); f1.y = fmaxf(fmaf(sA.y, f1.y, hA.y), 0.f);
      f4.x = fmaxf(fmaf(sA.x, f4.x, hA.x), 0.f); f4.y = fmaxf(fmaf(sA.y, f4.y, hA.y), 0.f);
      f5.x = fmaxf(fmaf(sA.x, f5.x, hA.x), 0.f); f5.y = fmaxf(fmaf(sA.y, f5.y, hA.y), 0.f);
      f2.x = fmaxf(fmaf(sB.x, f2.x, hB.x), 0.f); f2.y = fmaxf(fmaf(sB.y, f2.y, hB.y), 0.f);
      f3.x = fmaxf(fmaf(sB.x, f3.x, hB.x), 0.f); f3.y = fmaxf(fmaf(sB.y, f3.y, hB.y), 0.f);
      f6.x = fmaxf(fmaf(sB.x, f6.x, hB.x), 0.f); f6.y = fmaxf(fmaf(sB.y, f6.y, hB.y), 0.f);
      f7.x = fmaxf(fmaf(sB.x, f7.x, hB.x), 0.f); f7.y = fmaxf(fmaf(sB.y, f7.y, hB.y), 0.f);
    }
    if (!ok0) { f0.x = f0.y = f2.x = f2.y = 0.f; }
    if (!ok1) { f1.x = f1.y = f3.x = f3.y = 0.f; }
    if (!ok2) { f4.x = f4.y = f6.x = f6.y = 0.f; }
    if (!ok3) { f5.x = f5.y = f7.x = f7.y = 0.f; }
    uint32_t ah[2][4], al[2][4];
    split2(f0.x, f0.y, ah[0][0], al[0][0]);
    split2(f1.x, f1.y, ah[0][1], al[0][1]);
    split2(f2.x, f2.y, ah[0][2], al[0][2]);
    split2(f3.x, f3.y, ah[0][3], al[0][3]);
    split2(f4.x, f4.y, ah[1][0], al[1][0]);
    split2(f5.x, f5.y, ah[1][1], al[1][1]);
    split2(f6.x, f6.y, ah[1][2], al[1][2]);
    split2(f7.x, f7.y, ah[1][3], al[1][3]);

    int chunk = (kk >> 3) + chunk_off;
    uint32_t boff = (uint32_t)((chunk ^ swz7) << 4);
    uint32_t bfr[2][4];
    ldsm4(bfr[0], rowb[0] + boff);
    ldsm4(bfr[1], rowb[1] + boff);
    // pass hh: 8 MMAs, all distinct accumulators
#pragma unroll
    for (int p = 0; p < 2; p++)
#pragma unroll
      for (int mt = 0; mt < 2; mt++) {
        mma_bf16(acc[mt * 4 + p * 2], ah[mt], bfr[p][0], bfr[p][1]);
        mma_bf16(acc[mt * 4 + p * 2 + 1], ah[mt], bfr[p][2], bfr[p][3]);
      }
    // pass lh
#pragma unroll
    for (int p = 0; p < 2; p++)
#pragma unroll
      for (int mt = 0; mt < 2; mt++) {
        mma_bf16(acc[mt * 4 + p * 2], al[mt], bfr[p][0], bfr[p][1]);
        mma_bf16(acc[mt * 4 + p * 2 + 1], al[mt], bfr[p][2], bfr[p][3]);
      }
    // reload B lo plane into same regs
    ldsm4(bfr[0], rowb[0] + boff + WSM_BYTES);
    ldsm4(bfr[1], rowb[1] + boff + WSM_BYTES);
    // pass hl
#pragma unroll
    for (int p = 0; p < 2; p++)
#pragma unroll
      for (int mt = 0; mt < 2; mt++) {
        mma_bf16(acc[mt * 4 + p * 2], ah[mt], bfr[p][0], bfr[p][1]);
        mma_bf16(acc[mt * 4 + p * 2 + 1], ah[mt], bfr[p][2], bfr[p][3]);
      }
  }

  // epilogue: store + deterministic per-block BN partial stats
#pragma unroll
  for (int nt = 0; nt < 4; nt++) {
    int col = cb + nt * 8 + kq2;
    float bc0 = biasS[col], bc1 = biasS[col + 1];
    float s0 = 0.f, s1 = 0.f, q0 = 0.f, q1 = 0.f;
#pragma unroll
    for (int mt = 0; mt < 2; mt++) {
      int rA = row0 + rb + mt * 16 + rq;
      bool va = mt ? ok2 : ok0;
      bool vb = mt ? ok3 : ok1;
      float* ap = acc[mt * 4 + nt];
      float y00 = ap[0] + bc0, y01 = ap[1] + bc1;
      float y10 = ap[2] + bc0, y11 = ap[3] + bc1;
      if (va) *reinterpret_cast<float2*>(out + (size_t)rA * 128 + col) = make_float2(y00, y01);
      if (vb) *reinterpret_cast<float2*>(out + (size_t)(rA + 8) * 128 + col) = make_float2(y10, y11);
      s0 += (va ? y00 : 0.f) + (vb ? y10 : 0.f);
      s1 += (va ? y01 : 0.f) + (vb ? y11 : 0.f);
      q0 += (va ? y00 * y00 : 0.f) + (vb ? y10 * y10 : 0.f);
      q1 += (va ? y01 * y01 : 0.f) + (vb ? y11 * y11 : 0.f);
    }
#pragma unroll
    for (int o = 16; o >= 4; o >>= 1) {
      s0 += __shfl_xor_sync(0xffffffffu, s0, o);
      s1 += __shfl_xor_sync(0xffffffffu, s1, o);
      q0 += __shfl_xor_sync(0xffffffffu, q0, o);
      q1 += __shfl_xor_sync(0xffffffffu, q1, o);
    }
    if (rq == 0) {
      int wp = w >> 2;
      ssum[wp * 128 + col] = s0;
      ssum[wp * 128 + col + 1] = s1;
      ssq[wp * 128 + col] = q0;
      ssq[wp * 128 + col + 1] = q1;
    }
  }
  __syncthreads();
  if (t < 128) {
    g_psum[blockIdx.x * 128 + t] = ssum[t] + ssum[128 + t];
    g_psq[blockIdx.x * 128 + t] = ssq[t] + ssq[128 + t];
  }
}

// ---------------- reduce partials + BN params (deterministic fixed order) ----------
__global__ void redparams_kernel(const float* __restrict__ gamma,
                                 const float* __restrict__ beta, int which) {
  __shared__ float ssum[8 * 128], ssq[8 * 128];
  int t = threadIdx.x;  // 1024
  int col = t & 127, sl = t >> 7;
  int b0 = sl * 98, b1 = b0 + 98;
  if (b1 > NBLK_G) b1 = NBLK_G;
  float s = 0.f, q = 0.f;
  for (int b = b0; b < b1; b++) {
    s += g_psum[b * 128 + col];
    q += g_psq[b * 128 + col];
  }
  ssum[sl * 128 + col] = s;
  ssq[sl * 128 + col] = q;
  __syncthreads();
  if (t < 128) {
    float S = 0.f, Q = 0.f;
#pragma unroll
    for (int j = 0; j < 8; j++) {
      S += ssum[j * 128 + t];
      Q += ssq[j * 128 + t];
    }
    float inv = 1.0f / (float)KNT;
    float mu = S * inv;
    float var = Q * inv - mu * mu;
    float r = rsqrtf(var + BN_EPS);
    float sc = gamma[t] * r;
    g_scale[which * 128 + t] = sc;
    g_shift[which * 128 + t] = beta[t] - mu * sc;
  }
}

__global__ void finalize_kernel(float* __restrict__ out) {
  int i = blockIdx.x * blockDim.x + threadIdx.x;
  if (i >= KNT * 32) return;
  int c = (i & 31) << 2;
  float4 v = reinterpret_cast<float4*>(out)[i];
  v.x = fmaxf(fmaf(g_scale[128 + c + 0], v.x, g_shift[128 + c + 0]), 0.f);
  v.y = fmaxf(fmaf(g_scale[128 + c + 1], v.y, g_shift[128 + c + 1]), 0.f);
  v.z = fmaxf(fmaf(g_scale[128 + c + 2], v.z, g_shift[128 + c + 2]), 0.f);
  v.w = fmaxf(fmaf(g_scale[128 + c + 3], v.w, g_shift[128 + c + 3]), 0.f);
  reinterpret_cast<float4*>(out)[i] = v;
}

// ---------------- launch ----------------
extern "C" void kernel_launch(void* const* d_in, const int* in_sizes, int n_in,
                              void* d_out, int out_size) {
  const float* x_s = (const float*)d_in[0];
  const float* x_t = (const float*)d_in[1];
  const int* src = (const int*)d_in[2];  // int32 (JAX x64 disabled)
  const int* dst = (const int*)d_in[3];
  const float* eps = (const float*)d_in[4];
  const float* W1 = (const float*)d_in[5];
  const float* b1 = (const float*)d_in[6];
  const float* g1 = (const float*)d_in[7];
  const float* be1 = (const float*)d_in[8];
  const float* W2 = (const float*)d_in[9];
  const float* b2 = (const float*)d_in[10];
  const float* g2 = (const float*)d_in[11];
  const float* be2 = (const float*)d_in[12];
  float* out = (float*)d_out;

  const int SMEM = 2 * WSM_BYTES + (128 * 3 + 512) * 4;  // 69120 B
  cudaFuncSetAttribute(gemm_kernel<1>, cudaFuncAttributeMaxDynamicSharedMemorySize, SMEM);
  cudaFuncSetAttribute(gemm_kernel<2>, cudaFuncAttributeMaxDynamicSharedMemorySize, SMEM);

  splitw_kernel<<<32, 256>>>(W1, W2);                                // #1 (resets g_bar)
  build_kernel<<<NBLK_B, 512>>>(src, dst);                           // #2 zero+hist+scan+scatter
  aggregate_kernel<<<(KNT * 32 + 255) / 256, 256>>>(x_s, x_t, eps);  // #3
  gemm_kernel<1><<<NBLK_G, 256, SMEM>>>(b1, nullptr);                // #4 (profiled slot)
  redparams_kernel<<<1, 1024>>>(g1, be1, 0);                         // #5
  gemm_kernel<2><<<NBLK_G, 256, SMEM>>>(b2, out);                    // #6
  redparams_kernel<<<1, 1024>>>(g2, be2, 1);                         // #7
  finalize_kernel<<<(KNT * 32 + 255) / 256, 256>>>(out);             // #8
}

// round 8
// speedup vs baseline: 1.0509x; 1.0509x over previous
#include <cuda_runtime.h>
#include <cuda_bf16.h>
#include <stdint.h>

#define KNS 100000
#define KNT 50000
#define KE  600000
#define KD  128
#define BN_EPS 1e-5f
#define NBLK_G 782     // ceil(KNT/64)
#define NBLK_B 98      // builder blocks (resident)

// ---------------- scratch (static device memory; no allocations) ----------------
__device__ float g_h[KNT * KD];
__device__ float g_y1[KNT * KD];
__device__ int   g_counts[KNT];
__device__ int   g_offsets[KNT + 1];
__device__ int   g_cursor[KNT];
__device__ int   g_srcs[KE];
__device__ float g_psum[NBLK_G * KD];
__device__ float g_psq[NBLK_G * KD];
__device__ float g_scale[2 * KD];
__device__ float g_shift[2 * KD];
__device__ int   g_bsum[128];
__device__ unsigned g_bar;
__device__ __align__(16) __nv_bfloat16 g_Wh[2 * KD * KD];
__device__ __align__(16) __nv_bfloat16 g_Wl[2 * KD * KD];

// ---------------- device-wide barrier (all NBLK_B blocks resident) ----------------
__device__ __forceinline__ void gridbar(unsigned target) {
  __syncthreads();
  if (threadIdx.x == 0) {
    __threadfence();
    atomicAdd(&g_bar, 1u);
    while (*((volatile unsigned*)&g_bar) < target) {}
  }
  __syncthreads();
}

// ---------------- precompute hi/lo bf16 split of weights; reset barrier ----------
__global__ void splitw_kernel(const float* __restrict__ W1,
                              const float* __restrict__ W2) {
  int i = blockIdx.x * 256 + threadIdx.x;  // 0..8191, 4 elems each
  if (i == 0) g_bar = 0;
  if (i >= 8192) return;
  const float* W = (i < 4096) ? W1 : W2;
  int local = (i < 4096) ? i : (i - 4096);
  float4 v = *reinterpret_cast<const float4*>(W + local * 4);
  float arr[4] = {v.x, v.y, v.z, v.w};
  int o = i * 4;
#pragma unroll
  for (int j = 0; j < 4; j++) {
    __nv_bfloat16 h = __float2bfloat16_rn(arr[j]);
    g_Wh[o + j] = h;
    g_Wl[o + j] = __float2bfloat16_rn(arr[j] - __bfloat162float(h));
  }
}

__device__ __forceinline__ int warp_incl_scan(int x, int lane) {
#pragma unroll
  for (int o = 1; o < 32; o <<= 1) {
    int y = __shfl_up_sync(0xffffffffu, x, o);
    if (lane >= o) x += y;
  }
  return x;
}

// ------- builder: zero + histogram + exclusive scan + scatter in ONE kernel -------
__global__ void build_kernel(const int* __restrict__ src, const int* __restrict__ dst) {
  __shared__ int ws[16];
  __shared__ int sbase;
  int t = threadIdx.x, b = blockIdx.x;
  int i = b * 512 + t;
  int lane = t & 31, w = t >> 5;

  if (i < KNT) g_counts[i] = 0;
  gridbar(NBLK_B);

  const int4* dst4 = reinterpret_cast<const int4*>(dst);
  for (int e = i; e < KE / 4; e += NBLK_B * 512) {
    int4 d = dst4[e];
    atomicAdd(&g_counts[d.x], 1);
    atomicAdd(&g_counts[d.y], 1);
    atomicAdd(&g_counts[d.z], 1);
    atomicAdd(&g_counts[d.w], 1);
  }
  gridbar(2 * NBLK_B);

  int v = (i < KNT) ? __ldcg(&g_counts[i]) : 0;
  int x = warp_incl_scan(v, lane);
  if (lane == 31) ws[w] = x;
  __syncthreads();
  if (t < 16) {
    int y = ws[t];
#pragma unroll
    for (int o = 1; o < 16; o <<= 1) {
      int z = __shfl_up_sync(0xffffu, y, o);
      if (t >= o) y += z;
    }
    ws[t] = y;
  }
  __syncthreads();
  int incl = x + (w > 0 ? ws[w - 1] : 0);
  int ex = incl - v;
  if (t == 511) g_bsum[b] = incl;
  gridbar(3 * NBLK_B);

  int contrib = (t < b) ? __ldcg(&g_bsum[t]) : 0;
#pragma unroll
  for (int o = 16; o; o >>= 1) contrib += __shfl_down_sync(0xffffffffu, contrib, o);
  if (lane == 0) ws[w] = contrib;
  __syncthreads();
  if (t == 0) {
    int s = 0;
#pragma unroll
    for (int j = 0; j < 16; j++) s += ws[j];
    sbase = s;
  }
  __syncthreads();
  int off = ex + sbase;
  if (i < KNT) {
    g_offsets[i] = off;
    g_cursor[i] = off;
  }
  if (b == 0 && t == 0) g_offsets[KNT] = KE;
  gridbar(4 * NBLK_B);

  const int4* src4 = reinterpret_cast<const int4*>(src);
  for (int e = i; e < KE / 4; e += NBLK_B * 512) {
    int4 s = src4[e];
    int4 d = dst4[e];
    g_srcs[atomicAdd(&g_cursor[d.x], 1)] = s.x;
    g_srcs[atomicAdd(&g_cursor[d.y], 1)] = s.y;
    g_srcs[atomicAdd(&g_cursor[d.z], 1)] = s.z;
    g_srcs[atomicAdd(&g_cursor[d.w], 1)] = s.w;
  }
}

// ---------------- aggregation: one warp per target, high occupancy ----------------
__global__ __launch_bounds__(256, 6) void aggregate_kernel(const float* __restrict__ xs,
                                                           const float* __restrict__ xt,
                                                           const float* __restrict__ eps) {
  int gw = (blockIdx.x * blockDim.x + threadIdx.x) >> 5;
  int lane = threadIdx.x & 31;
  if (gw >= KNT) return;
  float sc = 1.0f + eps[0];
  const float4* xs4 = reinterpret_cast<const float4*>(xs);
  float4 a = reinterpret_cast<const float4*>(xt)[(size_t)gw * 32 + lane];
  a.x *= sc; a.y *= sc; a.z *= sc; a.w *= sc;
  float4 a1 = make_float4(0.f, 0.f, 0.f, 0.f);
  float4 a2 = make_float4(0.f, 0.f, 0.f, 0.f);
  float4 a3 = make_float4(0.f, 0.f, 0.f, 0.f);
  int beg = g_offsets[gw], end = g_offsets[gw + 1];
  int i = beg;
  for (; i + 3 < end; i += 4) {
    int s0 = g_srcs[i], s1 = g_srcs[i + 1], s2 = g_srcs[i + 2], s3 = g_srcs[i + 3];
    float4 v0 = xs4[(size_t)s0 * 32 + lane];
    float4 v1 = xs4[(size_t)s1 * 32 + lane];
    float4 v2 = xs4[(size_t)s2 * 32 + lane];
    float4 v3 = xs4[(size_t)s3 * 32 + lane];
    a.x += v0.x;  a.y += v0.y;  a.z += v0.z;  a.w += v0.w;
    a1.x += v1.x; a1.y += v1.y; a1.z += v1.z; a1.w += v1.w;
    a2.x += v2.x; a2.y += v2.y; a2.z += v2.z; a2.w += v2.w;
    a3.x += v3.x; a3.y += v3.y; a3.z += v3.z; a3.w += v3.w;
  }
  for (; i < end; i++) {
    float4 v0 = xs4[(size_t)g_srcs[i] * 32 + lane];
    a.x += v0.x; a.y += v0.y; a.z += v0.z; a.w += v0.w;
  }
  a.x += a1.x + a2.x + a3.x;
  a.y += a1.y + a2.y + a3.y;
  a.z += a1.z + a2.z + a3.z;
  a.w += a1.w + a2.w + a3.w;
  reinterpret_cast<float4*>(g_h)[(size_t)gw * 32 + lane] = a;
}

// ------- GEMM: all-smem (A staged once, coalesced), ldmatrix A+B, hi/lo split ------
__device__ __forceinline__ void mma_bf16(float* c, const uint32_t* a,
                                         uint32_t b0, uint32_t b1) {
  asm volatile(
      "mma.sync.aligned.m16n8k16.row.col.f32.bf16.bf16.f32 "
      "{%0,%1,%2,%3}, {%4,%5,%6,%7}, {%8,%9}, {%0,%1,%2,%3};\n"
      : "+f"(c[0]), "+f"(c[1]), "+f"(c[2]), "+f"(c[3])
      : "r"(a[0]), "r"(a[1]), "r"(a[2]), "r"(a[3]), "r"(b0), "r"(b1));
}

__device__ __forceinline__ void ldsm4(uint32_t* r, uint32_t addr) {
  asm volatile("ldmatrix.sync.aligned.m8n8.x4.shared.b16 {%0,%1,%2,%3}, [%4];"
               : "=r"(r[0]), "=r"(r[1]), "=r"(r[2]), "=r"(r[3]) : "r"(addr));
}

__device__ __forceinline__ void split2(float x0, float x1, uint32_t& hi, uint32_t& lo) {
  __nv_bfloat162 H = __floats2bfloat162_rn(x0, x1);
  float l0 = x0 - __bfloat162float(H.x);
  float l1 = x1 - __bfloat162float(H.y);
  __nv_bfloat162 L = __floats2bfloat162_rn(l0, l1);
  hi = *reinterpret_cast<uint32_t*>(&H);
  lo = *reinterpret_cast<uint32_t*>(&L);
}

#define WSM_BYTES 32768
#define ASM_BYTES 16384
template <int LAYER>
__global__ __launch_bounds__(256, 2) void gemm_kernel(const float* __restrict__ bias,
                                                      float* __restrict__ out_param) {
  extern __shared__ char sm[];
  char* WhS = sm;                         // [0,32K) W hi, [32K,64K) W lo
  char* AhS = sm + 2 * WSM_BYTES;         // [64K,80K) A hi, [80K,96K) A lo
  float* biasS = reinterpret_cast<float*>(sm + 2 * WSM_BYTES + 2 * ASM_BYTES);  // 128
  float* ssum = biasS + 128;              // 2*128
  float* ssq = ssum + 256;                // 2*128

  const float* A = (LAYER == 1) ? g_h : g_y1;
  float* out = (LAYER == 1) ? g_y1 : out_param;
  const __nv_bfloat16* GWh = g_Wh + (LAYER - 1) * KD * KD;
  const __nv_bfloat16* GWl = g_Wl + (LAYER - 1) * KD * KD;

  int t = threadIdx.x;
  int row0 = blockIdx.x * 64;
  int w = t >> 5, lane = t & 31;

  if (t < 128) biasS[t] = bias[t];

  // stage W hi/lo into swizzled smem: row r, 16B chunk c -> chunk c^(r&7)
  for (int idx = t; idx < 2048; idx += 256) {
    int r = idx >> 4, c = idx & 15;
    int db = r * 256 + ((c ^ (r & 7)) << 4);
    *reinterpret_cast<uint4*>(WhS + db) = reinterpret_cast<const uint4*>(GWh)[idx];
    *reinterpret_cast<uint4*>(WhS + WSM_BYTES + db) = reinterpret_cast<const uint4*>(GWl)[idx];
  }
  // stage A (64x128 fp32) once, coalesced; split to bf16 hi/lo planes (same swizzle)
  for (int idx = t; idx < 2048; idx += 256) {
    int r = idx >> 5, c4 = idx & 31;  // row, float4 index
    int grow = row0 + r;
    float4 v = make_float4(0.f, 0.f, 0.f, 0.f);
    if (grow < KNT) v = *reinterpret_cast<const float4*>(A + (size_t)grow * 128 + c4 * 4);
    if (LAYER == 2) {
      int c = c4 * 4;
      v.x = fmaxf(fmaf(__ldg(&g_scale[c + 0]), v.x, __ldg(&g_shift[c + 0])), 0.f);
      v.y = fmaxf(fmaf(__ldg(&g_scale[c + 1]), v.y, __ldg(&g_shift[c + 1])), 0.f);
      v.z = fmaxf(fmaf(__ldg(&g_scale[c + 2]), v.z, __ldg(&g_shift[c + 2])), 0.f);
      v.w = fmaxf(fmaf(__ldg(&g_scale[c + 3]), v.w, __ldg(&g_shift[c + 3])), 0.f);
    }
    uint32_t h0, l0, h1, l1;
    split2(v.x, v.y, h0, l0);
    split2(v.z, v.w, h1, l1);
    int chunk = c4 >> 1, sub = (c4 & 1) << 3;
    int db = r * 256 + ((chunk ^ (r & 7)) << 4) + sub;
    *reinterpret_cast<uint2*>(AhS + db) = make_uint2(h0, h1);
    *reinterpret_cast<uint2*>(AhS + ASM_BYTES + db) = make_uint2(l0, l1);
  }
  __syncthreads();

  int rq = lane >> 2;          // 0..7 (epilogue)
  int kq2 = (lane & 3) << 1;   // 0,2,4,6 (epilogue)
  int rb = (w >> 2) * 32;      // 2 row groups of 32
  int cb = (w & 3) * 32;       // 4 col groups of 32

  // B ldmatrix geometry
  int n_lane = (lane & 7) + ((lane >> 4) << 3);
  int bchoff = (lane >> 3) & 1;
  int bswz = n_lane & 7;
  uint32_t wbase = (uint32_t)__cvta_generic_to_shared(WhS);
  uint32_t browaddr[2];
#pragma unroll
  for (int p = 0; p < 2; p++) browaddr[p] = wbase + (cb + p * 16 + n_lane) * 256;

  // A ldmatrix geometry
  int a15 = lane & 15, achoff = lane >> 4, aswz = lane & 7;
  uint32_t abase = (uint32_t)__cvta_generic_to_shared(AhS);
  uint32_t arowaddr[2];
#pragma unroll
  for (int mt = 0; mt < 2; mt++) arowaddr[mt] = abase + (rb + mt * 16 + a15) * 256;

  float acc[8][4];  // [mt*4 + p*2 + j]
#pragma unroll
  for (int i = 0; i < 8; i++)
#pragma unroll
    for (int j = 0; j < 4; j++) acc[i][j] = 0.f;

#pragma unroll
  for (int kk = 0; kk < 128; kk += 16) {
    int kc = kk >> 3;
    uint32_t aoff = (uint32_t)(((kc + achoff) ^ aswz) << 4);
    uint32_t boff = (uint32_t)(((kc + bchoff) ^ bswz) << 4);
    uint32_t ah[2][4], al[2][4], bh[2][4], bl[2][4];
    ldsm4(ah[0], arowaddr[0] + aoff);
    ldsm4(ah[1], arowaddr[1] + aoff);
    ldsm4(al[0], arowaddr[0] + aoff + ASM_BYTES);
    ldsm4(al[1], arowaddr[1] + aoff + ASM_BYTES);
    ldsm4(bh[0], browaddr[0] + boff);
    ldsm4(bh[1], browaddr[1] + boff);
    ldsm4(bl[0], browaddr[0] + boff + WSM_BYTES);
    ldsm4(bl[1], browaddr[1] + boff + WSM_BYTES);
    // pass hh: 8 MMAs, distinct accumulators
#pragma unroll
    for (int p = 0; p < 2; p++)
#pragma unroll
      for (int mt = 0; mt < 2; mt++) {
        mma_bf16(acc[mt * 4 + p * 2], ah[mt], bh[p][0], bh[p][1]);
        mma_bf16(acc[mt * 4 + p * 2 + 1], ah[mt], bh[p][2], bh[p][3]);
      }
    // pass lh
#pragma unroll
    for (int p = 0; p < 2; p++)
#pragma unroll
      for (int mt = 0; mt < 2; mt++) {
        mma_bf16(acc[mt * 4 + p * 2], al[mt], bh[p][0], bh[p][1]);
        mma_bf16(acc[mt * 4 + p * 2 + 1], al[mt], bh[p][2], bh[p][3]);
      }
    // pass hl
#pragma unroll
    for (int p = 0; p < 2; p++)
#pragma unroll
      for (int mt = 0; mt < 2; mt++) {
        mma_bf16(acc[mt * 4 + p * 2], ah[mt], bl[p][0], bl[p][1]);
        mma_bf16(acc[mt * 4 + p * 2 + 1], ah[mt], bl[p][2], bl[p][3]);
      }
  }

  // epilogue: store + deterministic per-block BN partial stats
  int r0 = row0 + rb + rq;
  int r1 = r0 + 16;
  bool ok0 = r0 < KNT, ok1 = (r0 + 8) < KNT, ok2 = r1 < KNT, ok3 = (r1 + 8) < KNT;
#pragma unroll
  for (int nt = 0; nt < 4; nt++) {
    int col = cb + nt * 8 + kq2;
    float bc0 = biasS[col], bc1 = biasS[col + 1];
    float s0 = 0.f, s1 = 0.f, q0 = 0.f, q1 = 0.f;
#pragma unroll
    for (int mt = 0; mt < 2; mt++) {
      int rA = row0 + rb + mt * 16 + rq;
      bool va = mt ? ok2 : ok0;
      bool vb = mt ? ok3 : ok1;
      float* ap = acc[mt * 4 + nt];
      float y00 = ap[0] + bc0, y01 = ap[1] + bc1;
      float y10 = ap[2] + bc0, y11 = ap[3] + bc1;
      if (va) *reinterpret_cast<float2*>(out + (size_t)rA * 128 + col) = make_float2(y00, y01);
      if (vb) *reinterpret_cast<float2*>(out + (size_t)(rA + 8) * 128 + col) = make_float2(y10, y11);
      s0 += (va ? y00 : 0.f) + (vb ? y10 : 0.f);
      s1 += (va ? y01 : 0.f) + (vb ? y11 : 0.f);
      q0 += (va ? y00 * y00 : 0.f) + (vb ? y10 * y10 : 0.f);
      q1 += (va ? y01 * y01 : 0.f) + (vb ? y11 * y11 : 0.f);
    }
#pragma unroll
    for (int o = 16; o >= 4; o >>= 1) {
      s0 += __shfl_xor_sync(0xffffffffu, s0, o);
      s1 += __shfl_xor_sync(0xffffffffu, s1, o);
      q0 += __shfl_xor_sync(0xffffffffu, q0, o);
      q1 += __shfl_xor_sync(0xffffffffu, q1, o);
    }
    if (rq == 0) {
      int wp = w >> 2;
      ssum[wp * 128 + col] = s0;
      ssum[wp * 128 + col + 1] = s1;
      ssq[wp * 128 + col] = q0;
      ssq[wp * 128 + col + 1] = q1;
    }
  }
  __syncthreads();
  if (t < 128) {
    g_psum[blockIdx.x * 128 + t] = ssum[t] + ssum[128 + t];
    g_psq[blockIdx.x * 128 + t] = ssq[t] + ssq[128 + t];
  }
}

// ---------------- reduce partials + BN params (deterministic fixed order) ----------
__global__ void redparams_kernel(const float* __restrict__ gamma,
                                 const float* __restrict__ beta, int which) {
  __shared__ float ssum[8 * 128], ssq[8 * 128];
  int t = threadIdx.x;  // 1024
  int col = t & 127, sl = t >> 7;
  int b0 = sl * 98, b1 = b0 + 98;
  if (b1 > NBLK_G) b1 = NBLK_G;
  float s = 0.f, q = 0.f;
  for (int b = b0; b < b1; b++) {
    s += g_psum[b * 128 + col];
    q += g_psq[b * 128 + col];
  }
  ssum[sl * 128 + col] = s;
  ssq[sl * 128 + col] = q;
  __syncthreads();
  if (t < 128) {
    float S = 0.f, Q = 0.f;
#pragma unroll
    for (int j = 0; j < 8; j++) {
      S += ssum[j * 128 + t];
      Q += ssq[j * 128 + t];
    }
    float inv = 1.0f / (float)KNT;
    float mu = S * inv;
    float var = Q * inv - mu * mu;
    float r = rsqrtf(var + BN_EPS);
    float sc = gamma[t] * r;
    g_scale[which * 128 + t] = sc;
    g_shift[which * 128 + t] = beta[t] - mu * sc;
  }
}

__global__ void finalize_kernel(float* __restrict__ out) {
  int i = blockIdx.x * blockDim.x + threadIdx.x;
  if (i >= KNT * 32) return;
  int c = (i & 31) << 2;
  float4 v = reinterpret_cast<float4*>(out)[i];
  v.x = fmaxf(fmaf(g_scale[128 + c + 0], v.x, g_shift[128 + c + 0]), 0.f);
  v.y = fmaxf(fmaf(g_scale[128 + c + 1], v.y, g_shift[128 + c + 1]), 0.f);
  v.z = fmaxf(fmaf(g_scale[128 + c + 2], v.z, g_shift[128 + c + 2]), 0.f);
  v.w = fmaxf(fmaf(g_scale[128 + c + 3], v.w, g_shift[128 + c + 3]), 0.f);
  reinterpret_cast<float4*>(out)[i] = v;
}

// ---------------- launch ----------------
extern "C" void kernel_launch(void* const* d_in, const int* in_sizes, int n_in,
                              void* d_out, int out_size) {
  const float* x_s = (const float*)d_in[0];
  const float* x_t = (const float*)d_in[1];
  const int* src = (const int*)d_in[2];  // int32 (JAX x64 disabled)
  const int* dst = (const int*)d_in[3];
  const float* eps = (const float*)d_in[4];
  const float* W1 = (const float*)d_in[5];
  const float* b1 = (const float*)d_in[6];
  const float* g1 = (const float*)d_in[7];
  const float* be1 = (const float*)d_in[8];
  const float* W2 = (const float*)d_in[9];
  const float* b2 = (const float*)d_in[10];
  const float* g2 = (const float*)d_in[11];
  const float* be2 = (const float*)d_in[12];
  float* out = (float*)d_out;

  const int SMEM = 2 * WSM_BYTES + 2 * ASM_BYTES + (128 + 512) * 4;  // 100928 B
  cudaFuncSetAttribute(gemm_kernel<1>, cudaFuncAttributeMaxDynamicSharedMemorySize, SMEM);
  cudaFuncSetAttribute(gemm_kernel<2>, cudaFuncAttributeMaxDynamicSharedMemorySize, SMEM);

  splitw_kernel<<<32, 256>>>(W1, W2);                                // #1 (resets g_bar)
  build_kernel<<<NBLK_B, 512>>>(src, dst);                           // #2 zero+hist+scan+scatter
  aggregate_kernel<<<(KNT * 32 + 255) / 256, 256>>>(x_s, x_t, eps);  // #3
  gemm_kernel<1><<<NBLK_G, 256, SMEM>>>(b1, nullptr);                // #4 (profiled slot)
  redparams_kernel<<<1, 1024>>>(g1, be1, 0);                         // #5
  gemm_kernel<2><<<NBLK_G, 256, SMEM>>>(b2, out);                    // #6
  redparams_kernel<<<1, 1024>>>(g2, be2, 1);                         // #7
  finalize_kernel<<<(KNT * 32 + 255) / 256, 256>>>(out);             // #8
}

// round 9
// speedup vs baseline: 1.1401x; 1.0849x over previous
#include <cuda_runtime.h>
#include <cuda_bf16.h>
#include <stdint.h>

#define KNS 100000
#define KNT 50000
#define KE  600000
#define KD  128
#define BN_EPS 1e-5f
#define NBLK_G 782     // ceil(KNT/64) row tiles
#define GRID_G 296     // persistent gemm blocks (2/SM)
#define NBLK_B 98      // builder blocks (resident)

// ---------------- scratch (static device memory; no allocations) ----------------
__device__ float g_h[KNT * KD];
__device__ float g_y1[KNT * KD];
__device__ int   g_counts[KNT];
__device__ int   g_offsets[KNT + 1];
__device__ int   g_cursor[KNT];
__device__ int   g_srcs[KE];
__device__ float g_psum[NBLK_G * KD];
__device__ float g_psq[NBLK_G * KD];
__device__ float g_scale[2 * KD];
__device__ float g_shift[2 * KD];
__device__ int   g_bsum[128];
__device__ unsigned g_bar;
__device__ __align__(16) __nv_bfloat16 g_Wh[2 * KD * KD];
__device__ __align__(16) __nv_bfloat16 g_Wl[2 * KD * KD];

// ---------------- device-wide barrier (all NBLK_B blocks resident) ----------------
__device__ __forceinline__ void gridbar(unsigned target) {
  __syncthreads();
  if (threadIdx.x == 0) {
    __threadfence();
    atomicAdd(&g_bar, 1u);
    while (*((volatile unsigned*)&g_bar) < target) {}
  }
  __syncthreads();
}

// ---------------- precompute hi/lo bf16 split of weights; reset barrier ----------
__global__ void splitw_kernel(const float* __restrict__ W1,
                              const float* __restrict__ W2) {
  int i = blockIdx.x * 256 + threadIdx.x;  // 0..8191, 4 elems each
  if (i == 0) g_bar = 0;
  if (i >= 8192) return;
  const float* W = (i < 4096) ? W1 : W2;
  int local = (i < 4096) ? i : (i - 4096);
  float4 v = *reinterpret_cast<const float4*>(W + local * 4);
  float arr[4] = {v.x, v.y, v.z, v.w};
  int o = i * 4;
#pragma unroll
  for (int j = 0; j < 4; j++) {
    __nv_bfloat16 h = __float2bfloat16_rn(arr[j]);
    g_Wh[o + j] = h;
    g_Wl[o + j] = __float2bfloat16_rn(arr[j] - __bfloat162float(h));
  }
}

__device__ __forceinline__ int warp_incl_scan(int x, int lane) {
#pragma unroll
  for (int o = 1; o < 32; o <<= 1) {
    int y = __shfl_up_sync(0xffffffffu, x, o);
    if (lane >= o) x += y;
  }
  return x;
}

// ------- builder: zero + histogram + exclusive scan + scatter in ONE kernel -------
__global__ void build_kernel(const int* __restrict__ src, const int* __restrict__ dst) {
  __shared__ int ws[16];
  __shared__ int sbase;
  int t = threadIdx.x, b = blockIdx.x;
  int i = b * 512 + t;
  int lane = t & 31, w = t >> 5;

  if (i < KNT) g_counts[i] = 0;
  gridbar(NBLK_B);

  const int4* dst4 = reinterpret_cast<const int4*>(dst);
  for (int e = i; e < KE / 4; e += NBLK_B * 512) {
    int4 d = dst4[e];
    atomicAdd(&g_counts[d.x], 1);
    atomicAdd(&g_counts[d.y], 1);
    atomicAdd(&g_counts[d.z], 1);
    atomicAdd(&g_counts[d.w], 1);
  }
  gridbar(2 * NBLK_B);

  int v = (i < KNT) ? __ldcg(&g_counts[i]) : 0;
  int x = warp_incl_scan(v, lane);
  if (lane == 31) ws[w] = x;
  __syncthreads();
  if (t < 16) {
    int y = ws[t];
#pragma unroll
    for (int o = 1; o < 16; o <<= 1) {
      int z = __shfl_up_sync(0xffffu, y, o);
      if (t >= o) y += z;
    }
    ws[t] = y;
  }
  __syncthreads();
  int incl = x + (w > 0 ? ws[w - 1] : 0);
  int ex = incl - v;
  if (t == 511) g_bsum[b] = incl;
  gridbar(3 * NBLK_B);

  int contrib = (t < b) ? __ldcg(&g_bsum[t]) : 0;
#pragma unroll
  for (int o = 16; o; o >>= 1) contrib += __shfl_down_sync(0xffffffffu, contrib, o);
  if (lane == 0) ws[w] = contrib;
  __syncthreads();
  if (t == 0) {
    int s = 0;
#pragma unroll
    for (int j = 0; j < 16; j++) s += ws[j];
    sbase = s;
  }
  __syncthreads();
  int off = ex + sbase;
  if (i < KNT) {
    g_offsets[i] = off;
    g_cursor[i] = off;
  }
  if (b == 0 && t == 0) g_offsets[KNT] = KE;
  gridbar(4 * NBLK_B);

  const int4* src4 = reinterpret_cast<const int4*>(src);
  for (int e = i; e < KE / 4; e += NBLK_B * 512) {
    int4 s = src4[e];
    int4 d = dst4[e];
    g_srcs[atomicAdd(&g_cursor[d.x], 1)] = s.x;
    g_srcs[atomicAdd(&g_cursor[d.y], 1)] = s.y;
    g_srcs[atomicAdd(&g_cursor[d.z], 1)] = s.z;
    g_srcs[atomicAdd(&g_cursor[d.w], 1)] = s.w;
  }
}

// ---------------- aggregation: one warp per target, high occupancy ----------------
__global__ __launch_bounds__(256, 6) void aggregate_kernel(const float* __restrict__ xs,
                                                           const float* __restrict__ xt,
                                                           const float* __restrict__ eps) {
  int gw = (blockIdx.x * blockDim.x + threadIdx.x) >> 5;
  int lane = threadIdx.x & 31;
  if (gw >= KNT) return;
  float sc = 1.0f + eps[0];
  const float4* xs4 = reinterpret_cast<const float4*>(xs);
  float4 a = reinterpret_cast<const float4*>(xt)[(size_t)gw * 32 + lane];
  a.x *= sc; a.y *= sc; a.z *= sc; a.w *= sc;
  float4 a1 = make_float4(0.f, 0.f, 0.f, 0.f);
  float4 a2 = make_float4(0.f, 0.f, 0.f, 0.f);
  float4 a3 = make_float4(0.f, 0.f, 0.f, 0.f);
  int beg = g_offsets[gw], end = g_offsets[gw + 1];
  int i = beg;
  for (; i + 3 < end; i += 4) {
    int s0 = g_srcs[i], s1 = g_srcs[i + 1], s2 = g_srcs[i + 2], s3 = g_srcs[i + 3];
    float4 v0 = xs4[(size_t)s0 * 32 + lane];
    float4 v1 = xs4[(size_t)s1 * 32 + lane];
    float4 v2 = xs4[(size_t)s2 * 32 + lane];
    float4 v3 = xs4[(size_t)s3 * 32 + lane];
    a.x += v0.x;  a.y += v0.y;  a.z += v0.z;  a.w += v0.w;
    a1.x += v1.x; a1.y += v1.y; a1.z += v1.z; a1.w += v1.w;
    a2.x += v2.x; a2.y += v2.y; a2.z += v2.z; a2.w += v2.w;
    a3.x += v3.x; a3.y += v3.y; a3.z += v3.z; a3.w += v3.w;
  }
  for (; i < end; i++) {
    float4 v0 = xs4[(size_t)g_srcs[i] * 32 + lane];
    a.x += v0.x; a.y += v0.y; a.z += v0.z; a.w += v0.w;
  }
  a.x += a1.x + a2.x + a3.x;
  a.y += a1.y + a2.y + a3.y;
  a.z += a1.z + a2.z + a3.z;
  a.w += a1.w + a2.w + a3.w;
  reinterpret_cast<float4*>(g_h)[(size_t)gw * 32 + lane] = a;
}

// ------- persistent GEMM: W staged ONCE per block, tiles looped, all-smem MMA ------
__device__ __forceinline__ void mma_bf16(float* c, const uint32_t* a,
                                         uint32_t b0, uint32_t b1) {
  asm volatile(
      "mma.sync.aligned.m16n8k16.row.col.f32.bf16.bf16.f32 "
      "{%0,%1,%2,%3}, {%4,%5,%6,%7}, {%8,%9}, {%0,%1,%2,%3};\n"
      : "+f"(c[0]), "+f"(c[1]), "+f"(c[2]), "+f"(c[3])
      : "r"(a[0]), "r"(a[1]), "r"(a[2]), "r"(a[3]), "r"(b0), "r"(b1));
}

__device__ __forceinline__ void ldsm4(uint32_t* r, uint32_t addr) {
  asm volatile("ldmatrix.sync.aligned.m8n8.x4.shared.b16 {%0,%1,%2,%3}, [%4];"
               : "=r"(r[0]), "=r"(r[1]), "=r"(r[2]), "=r"(r[3]) : "r"(addr));
}

__device__ __forceinline__ void split2(float x0, float x1, uint32_t& hi, uint32_t& lo) {
  __nv_bfloat162 H = __floats2bfloat162_rn(x0, x1);
  float l0 = x0 - __bfloat162float(H.x);
  float l1 = x1 - __bfloat162float(H.y);
  __nv_bfloat162 L = __floats2bfloat162_rn(l0, l1);
  hi = *reinterpret_cast<uint32_t*>(&H);
  lo = *reinterpret_cast<uint32_t*>(&L);
}

#define WSM_BYTES 32768
#define ASM_BYTES 16384
template <int LAYER>
__global__ __launch_bounds__(256, 2) void gemm_kernel(const float* __restrict__ bias,
                                                      float* __restrict__ out_param) {
  extern __shared__ char sm[];
  char* WhS = sm;                         // [0,32K) W hi, [32K,64K) W lo
  char* AhS = sm + 2 * WSM_BYTES;         // [64K,80K) A hi, [80K,96K) A lo
  float* biasS = reinterpret_cast<float*>(sm + 2 * WSM_BYTES + 2 * ASM_BYTES);  // 128
  float* ssum = biasS + 128;              // 2*128
  float* ssq = ssum + 256;                // 2*128

  const float* A = (LAYER == 1) ? g_h : g_y1;
  float* out = (LAYER == 1) ? g_y1 : out_param;
  const __nv_bfloat16* GWh = g_Wh + (LAYER - 1) * KD * KD;
  const __nv_bfloat16* GWl = g_Wl + (LAYER - 1) * KD * KD;

  int t = threadIdx.x;
  int w = t >> 5, lane = t & 31;

  if (t < 128) biasS[t] = bias[t];

  // ---- stage W hi/lo ONCE: row r, 16B chunk c -> chunk c^(r&7) ----
  for (int idx = t; idx < 2048; idx += 256) {
    int r = idx >> 4, c = idx & 15;
    int db = r * 256 + ((c ^ (r & 7)) << 4);
    *reinterpret_cast<uint4*>(WhS + db) = reinterpret_cast<const uint4*>(GWh)[idx];
    *reinterpret_cast<uint4*>(WhS + WSM_BYTES + db) = reinterpret_cast<const uint4*>(GWl)[idx];
  }

  // thread-invariant geometry
  int rq = lane >> 2;          // 0..7 (epilogue)
  int kq2 = (lane & 3) << 1;   // 0,2,4,6 (epilogue)
  int rb = (w >> 2) * 32;      // 2 row groups of 32
  int cb = (w & 3) * 32;       // 4 col groups of 32
  int n_lane = (lane & 7) + ((lane >> 4) << 3);
  int bchoff = (lane >> 3) & 1;
  int bswz = n_lane & 7;
  uint32_t wbase = (uint32_t)__cvta_generic_to_shared(WhS);
  uint32_t browaddr[2];
#pragma unroll
  for (int p = 0; p < 2; p++) browaddr[p] = wbase + (cb + p * 16 + n_lane) * 256;
  int a15 = lane & 15, achoff = lane >> 4, aswz = lane & 7;
  uint32_t abase = (uint32_t)__cvta_generic_to_shared(AhS);
  uint32_t arowaddr[2];
#pragma unroll
  for (int mt = 0; mt < 2; mt++) arowaddr[mt] = abase + (rb + mt * 16 + a15) * 256;

  // ---- persistent tile loop ----
  for (int tile = blockIdx.x; tile < NBLK_G; tile += GRID_G) {
    int row0 = tile * 64;
    __syncthreads();  // planes free (prev compute done), W staged (first iter)

    // stage A (64x128 fp32), coalesced; split to bf16 hi/lo planes (same swizzle)
    for (int idx = t; idx < 2048; idx += 256) {
      int r = idx >> 5, c4 = idx & 31;
      int grow = row0 + r;
      float4 v = make_float4(0.f, 0.f, 0.f, 0.f);
      if (grow < KNT) v = *reinterpret_cast<const float4*>(A + (size_t)grow * 128 + c4 * 4);
      if (LAYER == 2) {
        int c = c4 * 4;
        v.x = fmaxf(fmaf(__ldg(&g_scale[c + 0]), v.x, __ldg(&g_shift[c + 0])), 0.f);
        v.y = fmaxf(fmaf(__ldg(&g_scale[c + 1]), v.y, __ldg(&g_shift[c + 1])), 0.f);
        v.z = fmaxf(fmaf(__ldg(&g_scale[c + 2]), v.z, __ldg(&g_shift[c + 2])), 0.f);
        v.w = fmaxf(fmaf(__ldg(&g_scale[c + 3]), v.w, __ldg(&g_shift[c + 3])), 0.f);
      }
      uint32_t h0, l0, h1, l1;
      split2(v.x, v.y, h0, l0);
      split2(v.z, v.w, h1, l1);
      int chunk = c4 >> 1, sub = (c4 & 1) << 3;
      int db = r * 256 + ((chunk ^ (r & 7)) << 4) + sub;
      *reinterpret_cast<uint2*>(AhS + db) = make_uint2(h0, h1);
      *reinterpret_cast<uint2*>(AhS + ASM_BYTES + db) = make_uint2(l0, l1);
    }
    __syncthreads();

    float acc[8][4];  // [mt*4 + p*2 + j]
#pragma unroll
    for (int i = 0; i < 8; i++)
#pragma unroll
      for (int j = 0; j < 4; j++) acc[i][j] = 0.f;

#pragma unroll
    for (int kk = 0; kk < 128; kk += 16) {
      int kc = kk >> 3;
      uint32_t aoff = (uint32_t)(((kc + achoff) ^ aswz) << 4);
      uint32_t boff = (uint32_t)(((kc + bchoff) ^ bswz) << 4);
      uint32_t ah[2][4], al[2][4], bh[2][4], bl[2][4];
      ldsm4(ah[0], arowaddr[0] + aoff);
      ldsm4(ah[1], arowaddr[1] + aoff);
      ldsm4(al[0], arowaddr[0] + aoff + ASM_BYTES);
      ldsm4(al[1], arowaddr[1] + aoff + ASM_BYTES);
      ldsm4(bh[0], browaddr[0] + boff);
      ldsm4(bh[1], browaddr[1] + boff);
      ldsm4(bl[0], browaddr[0] + boff + WSM_BYTES);
      ldsm4(bl[1], browaddr[1] + boff + WSM_BYTES);
#pragma unroll
      for (int p = 0; p < 2; p++)
#pragma unroll
        for (int mt = 0; mt < 2; mt++) {
          mma_bf16(acc[mt * 4 + p * 2], ah[mt], bh[p][0], bh[p][1]);
          mma_bf16(acc[mt * 4 + p * 2 + 1], ah[mt], bh[p][2], bh[p][3]);
        }
#pragma unroll
      for (int p = 0; p < 2; p++)
#pragma unroll
        for (int mt = 0; mt < 2; mt++) {
          mma_bf16(acc[mt * 4 + p * 2], al[mt], bh[p][0], bh[p][1]);
          mma_bf16(acc[mt * 4 + p * 2 + 1], al[mt], bh[p][2], bh[p][3]);
        }
#pragma unroll
      for (int p = 0; p < 2; p++)
#pragma unroll
        for (int mt = 0; mt < 2; mt++) {
          mma_bf16(acc[mt * 4 + p * 2], ah[mt], bl[p][0], bl[p][1]);
          mma_bf16(acc[mt * 4 + p * 2 + 1], ah[mt], bl[p][2], bl[p][3]);
        }
    }

    // epilogue: store + deterministic per-tile BN partial stats
    int r0 = row0 + rb + rq;
    int r1 = r0 + 16;
    bool ok0 = r0 < KNT, ok1 = (r0 + 8) < KNT, ok2 = r1 < KNT, ok3 = (r1 + 8) < KNT;
#pragma unroll
    for (int nt = 0; nt < 4; nt++) {
      int col = cb + nt * 8 + kq2;
      float bc0 = biasS[col], bc1 = biasS[col + 1];
      float s0 = 0.f, s1 = 0.f, q0 = 0.f, q1 = 0.f;
#pragma unroll
      for (int mt = 0; mt < 2; mt++) {
        int rA = row0 + rb + mt * 16 + rq;
        bool va = mt ? ok2 : ok0;
        bool vb = mt ? ok3 : ok1;
        float* ap = acc[mt * 4 + nt];
        float y00 = ap[0] + bc0, y01 = ap[1] + bc1;
        float y10 = ap[2] + bc0, y11 = ap[3] + bc1;
        if (va) *reinterpret_cast<float2*>(out + (size_t)rA * 128 + col) = make_float2(y00, y01);
        if (vb) *reinterpret_cast<float2*>(out + (size_t)(rA + 8) * 128 + col) = make_float2(y10, y11);
        s0 += (va ? y00 : 0.f) + (vb ? y10 : 0.f);
        s1 += (va ? y01 : 0.f) + (vb ? y11 : 0.f);
        q0 += (va ? y00 * y00 : 0.f) + (vb ? y10 * y10 : 0.f);
        q1 += (va ? y01 * y01 : 0.f) + (vb ? y11 * y11 : 0.f);
      }
#pragma unroll
      for (int o = 16; o >= 4; o >>= 1) {
        s0 += __shfl_xor_sync(0xffffffffu, s0, o);
        s1 += __shfl_xor_sync(0xffffffffu, s1, o);
        q0 += __shfl_xor_sync(0xffffffffu, q0, o);
        q1 += __shfl_xor_sync(0xffffffffu, q1, o);
      }
      if (rq == 0) {
        int wp = w >> 2;
        ssum[wp * 128 + col] = s0;
        ssum[wp * 128 + col + 1] = s1;
        ssq[wp * 128 + col] = q0;
        ssq[wp * 128 + col + 1] = q1;
      }
    }
    __syncthreads();
    if (t < 128) {
      g_psum[tile * 128 + t] = ssum[t] + ssum[128 + t];
      g_psq[tile * 128 + t] = ssq[t] + ssq[128 + t];
    }
  }
}

// ---------------- reduce partials + BN params (deterministic fixed order) ----------
__global__ void redparams_kernel(const float* __restrict__ gamma,
                                 const float* __restrict__ beta, int which) {
  __shared__ float ssum[8 * 128], ssq[8 * 128];
  int t = threadIdx.x;  // 1024
  int col = t & 127, sl = t >> 7;
  int b0 = sl * 98, b1 = b0 + 98;
  if (b1 > NBLK_G) b1 = NBLK_G;
  float s = 0.f, q = 0.f;
  for (int b = b0; b < b1; b++) {
    s += g_psum[b * 128 + col];
    q += g_psq[b * 128 + col];
  }
  ssum[sl * 128 + col] = s;
  ssq[sl * 128 + col] = q;
  __syncthreads();
  if (t < 128) {
    float S = 0.f, Q = 0.f;
#pragma unroll
    for (int j = 0; j < 8; j++) {
      S += ssum[j * 128 + t];
      Q += ssq[j * 128 + t];
    }
    float inv = 1.0f / (float)KNT;
    float mu = S * inv;
    float var = Q * inv - mu * mu;
    float r = rsqrtf(var + BN_EPS);
    float sc = gamma[t] * r;
    g_scale[which * 128 + t] = sc;
    g_shift[which * 128 + t] = beta[t] - mu * sc;
  }
}

__global__ void finalize_kernel(float* __restrict__ out) {
  int i = blockIdx.x * blockDim.x + threadIdx.x;
  if (i >= KNT * 32) return;
  int c = (i & 31) << 2;
  float4 v = reinterpret_cast<float4*>(out)[i];
  v.x = fmaxf(fmaf(g_scale[128 + c + 0], v.x, g_shift[128 + c + 0]), 0.f);
  v.y = fmaxf(fmaf(g_scale[128 + c + 1], v.y, g_shift[128 + c + 1]), 0.f);
  v.z = fmaxf(fmaf(g_scale[128 + c + 2], v.z, g_shift[128 + c + 2]), 0.f);
  v.w = fmaxf(fmaf(g_scale[128 + c + 3], v.w, g_shift[128 + c + 3]), 0.f);
  reinterpret_cast<float4*>(out)[i] = v;
}

// ---------------- launch ----------------
extern "C" void kernel_launch(void* const* d_in, const int* in_sizes, int n_in,
                              void* d_out, int out_size) {
  const float* x_s = (const float*)d_in[0];
  const float* x_t = (const float*)d_in[1];
  const int* src = (const int*)d_in[2];  // int32 (JAX x64 disabled)
  const int* dst = (const int*)d_in[3];
  const float* eps = (const float*)d_in[4];
  const float* W1 = (const float*)d_in[5];
  const float* b1 = (const float*)d_in[6];
  const float* g1 = (const float*)d_in[7];
  const float* be1 = (const float*)d_in[8];
  const float* W2 = (const float*)d_in[9];
  const float* b2 = (const float*)d_in[10];
  const float* g2 = (const float*)d_in[11];
  const float* be2 = (const float*)d_in[12];
  float* out = (float*)d_out;

  const int SMEM = 2 * WSM_BYTES + 2 * ASM_BYTES + (128 + 512) * 4;  // 100928 B
  cudaFuncSetAttribute(gemm_kernel<1>, cudaFuncAttributeMaxDynamicSharedMemorySize, SMEM);
  cudaFuncSetAttribute(gemm_kernel<2>, cudaFuncAttributeMaxDynamicSharedMemorySize, SMEM);

  splitw_kernel<<<32, 256>>>(W1, W2);                                // #1 (resets g_bar)
  build_kernel<<<NBLK_B, 512>>>(src, dst);                           // #2 zero+hist+scan+scatter
  aggregate_kernel<<<(KNT * 32 + 255) / 256, 256>>>(x_s, x_t, eps);  // #3
  gemm_kernel<1><<<GRID_G, 256, SMEM>>>(b1, nullptr);                // #4 (profiled slot)
  redparams_kernel<<<1, 1024>>>(g1, be1, 0);                         // #5
  gemm_kernel<2><<<GRID_G, 256, SMEM>>>(b2, out);                    // #6
  redparams_kernel<<<1, 1024>>>(g2, be2, 1);                         // #7
  finalize_kernel<<<(KNT * 32 + 255) / 256, 256>>>(out);             // #8
}

// round 11
// speedup vs baseline: 1.1940x; 1.0473x over previous
#include <cuda_runtime.h>
#include <cuda_bf16.h>
#include <stdint.h>

#define KNS 100000
#define KNT 50000
#define KE  600000
#define KD  128
#define BN_EPS 1e-5f
#define NBLK_G 782     // ceil(KNT/64) row tiles
#define GRID_G 296     // persistent gemm blocks (2/SM)
#define NBLK_B 98      // builder blocks (resident)

// ---------------- scratch (static device memory; no allocations) ----------------
__device__ float g_h[KNT * KD];
__device__ float g_y1[KNT * KD];
__device__ int   g_counts[KNT];
__device__ int   g_offsets[KNT + 1];
__device__ int   g_cursor[KNT];
__device__ int   g_srcs[KE];
__device__ float g_psum[NBLK_G * KD];
__device__ float g_psq[NBLK_G * KD];
__device__ float g_scale[2 * KD];
__device__ float g_shift[2 * KD];
__device__ int   g_bsum[128];
__device__ unsigned g_bar;
__device__ __align__(16) __nv_bfloat16 g_Wh[2 * KD * KD];
__device__ __align__(16) __nv_bfloat16 g_Wl[2 * KD * KD];

// ---------------- device-wide barrier (all NBLK_B blocks resident) ----------------
__device__ __forceinline__ void gridbar(unsigned target) {
  __syncthreads();
  if (threadIdx.x == 0) {
    __threadfence();
    atomicAdd(&g_bar, 1u);
    while (*((volatile unsigned*)&g_bar) < target) {}
  }
  __syncthreads();
}

// ---------------- precompute hi/lo bf16 split of weights; reset barrier ----------
__global__ void splitw_kernel(const float* __restrict__ W1,
                              const float* __restrict__ W2) {
  int i = blockIdx.x * 256 + threadIdx.x;  // 0..8191, 4 elems each
  if (i == 0) g_bar = 0;
  if (i >= 8192) return;
  const float* W = (i < 4096) ? W1 : W2;
  int local = (i < 4096) ? i : (i - 4096);
  float4 v = *reinterpret_cast<const float4*>(W + local * 4);
  float arr[4] = {v.x, v.y, v.z, v.w};
  int o = i * 4;
#pragma unroll
  for (int j = 0; j < 4; j++) {
    __nv_bfloat16 h = __float2bfloat16_rn(arr[j]);
    g_Wh[o + j] = h;
    g_Wl[o + j] = __float2bfloat16_rn(arr[j] - __bfloat162float(h));
  }
}

__device__ __forceinline__ int warp_incl_scan(int x, int lane) {
#pragma unroll
  for (int o = 1; o < 32; o <<= 1) {
    int y = __shfl_up_sync(0xffffffffu, x, o);
    if (lane >= o) x += y;
  }
  return x;
}

// ------- builder: zero + histogram + exclusive scan + scatter in ONE kernel -------
__global__ void build_kernel(const int* __restrict__ src, const int* __restrict__ dst) {
  __shared__ int ws[16];
  __shared__ int sbase;
  int t = threadIdx.x, b = blockIdx.x;
  int i = b * 512 + t;
  int lane = t & 31, w = t >> 5;

  if (i < KNT) g_counts[i] = 0;
  gridbar(NBLK_B);

  const int4* dst4 = reinterpret_cast<const int4*>(dst);
  for (int e = i; e < KE / 4; e += NBLK_B * 512) {
    int4 d = dst4[e];
    atomicAdd(&g_counts[d.x], 1);
    atomicAdd(&g_counts[d.y], 1);
    atomicAdd(&g_counts[d.z], 1);
    atomicAdd(&g_counts[d.w], 1);
  }
  gridbar(2 * NBLK_B);

  int v = (i < KNT) ? __ldcg(&g_counts[i]) : 0;
  int x = warp_incl_scan(v, lane);
  if (lane == 31) ws[w] = x;
  __syncthreads();
  if (t < 16) {
    int y = ws[t];
#pragma unroll
    for (int o = 1; o < 16; o <<= 1) {
      int z = __shfl_up_sync(0xffffu, y, o);
      if (t >= o) y += z;
    }
    ws[t] = y;
  }
  __syncthreads();
  int incl = x + (w > 0 ? ws[w - 1] : 0);
  int ex = incl - v;
  if (t == 511) g_bsum[b] = incl;
  gridbar(3 * NBLK_B);

  int contrib = (t < b) ? __ldcg(&g_bsum[t]) : 0;
#pragma unroll
  for (int o = 16; o; o >>= 1) contrib += __shfl_down_sync(0xffffffffu, contrib, o);
  if (lane == 0) ws[w] = contrib;
  __syncthreads();
  if (t == 0) {
    int s = 0;
#pragma unroll
    for (int j = 0; j < 16; j++) s += ws[j];
    sbase = s;
  }
  __syncthreads();
  int off = ex + sbase;
  if (i < KNT) {
    g_offsets[i] = off;
    g_cursor[i] = off;
  }
  if (b == 0 && t == 0) g_offsets[KNT] = KE;
  gridbar(4 * NBLK_B);

  const int4* src4 = reinterpret_cast<const int4*>(src);
  for (int e = i; e < KE / 4; e += NBLK_B * 512) {
    int4 s = src4[e];
    int4 d = dst4[e];
    g_srcs[atomicAdd(&g_cursor[d.x], 1)] = s.x;
    g_srcs[atomicAdd(&g_cursor[d.y], 1)] = s.y;
    g_srcs[atomicAdd(&g_cursor[d.z], 1)] = s.z;
    g_srcs[atomicAdd(&g_cursor[d.w], 1)] = s.w;
  }
}

// ---------------- aggregation: one warp per target, high occupancy ----------------
__global__ __launch_bounds__(256, 6) void aggregate_kernel(const float* __restrict__ xs,
                                                           const float* __restrict__ xt,
                                                           const float* __restrict__ eps) {
  int gw = (blockIdx.x * blockDim.x + threadIdx.x) >> 5;
  int lane = threadIdx.x & 31;
  if (gw >= KNT) return;
  float sc = 1.0f + eps[0];
  const float4* xs4 = reinterpret_cast<const float4*>(xs);
  float4 a = reinterpret_cast<const float4*>(xt)[(size_t)gw * 32 + lane];
  a.x *= sc; a.y *= sc; a.z *= sc; a.w *= sc;
  float4 a1 = make_float4(0.f, 0.f, 0.f, 0.f);
  float4 a2 = make_float4(0.f, 0.f, 0.f, 0.f);
  float4 a3 = make_float4(0.f, 0.f, 0.f, 0.f);
  int beg = g_offsets[gw], end = g_offsets[gw + 1];
  int i = beg;
  for (; i + 3 < end; i += 4) {
    int s0 = g_srcs[i], s1 = g_srcs[i + 1], s2 = g_srcs[i + 2], s3 = g_srcs[i + 3];
    float4 v0 = xs4[(size_t)s0 * 32 + lane];
    float4 v1 = xs4[(size_t)s1 * 32 + lane];
    float4 v2 = xs4[(size_t)s2 * 32 + lane];
    float4 v3 = xs4[(size_t)s3 * 32 + lane];
    a.x += v0.x;  a.y += v0.y;  a.z += v0.z;  a.w += v0.w;
    a1.x += v1.x; a1.y += v1.y; a1.z += v1.z; a1.w += v1.w;
    a2.x += v2.x; a2.y += v2.y; a2.z += v2.z; a2.w += v2.w;
    a3.x += v3.x; a3.y += v3.y; a3.z += v3.z; a3.w += v3.w;
  }
  for (; i < end; i++) {
    float4 v0 = xs4[(size_t)g_srcs[i] * 32 + lane];
    a.x += v0.x; a.y += v0.y; a.z += v0.z; a.w += v0.w;
  }
  a.x += a1.x + a2.x + a3.x;
  a.y += a1.y + a2.y + a3.y;
  a.z += a1.z + a2.z + a3.z;
  a.w += a1.w + a2.w + a3.w;
  reinterpret_cast<float4*>(g_h)[(size_t)gw * 32 + lane] = a;
}

// ------- persistent GEMM: W once (cp.async), pipelined LDSM/MMA mainloop ----------
__device__ __forceinline__ void mma_bf16(float* c, const uint32_t* a,
                                         uint32_t b0, uint32_t b1) {
  asm volatile(
      "mma.sync.aligned.m16n8k16.row.col.f32.bf16.bf16.f32 "
      "{%0,%1,%2,%3}, {%4,%5,%6,%7}, {%8,%9}, {%0,%1,%2,%3};\n"
      : "+f"(c[0]), "+f"(c[1]), "+f"(c[2]), "+f"(c[3])
      : "r"(a[0]), "r"(a[1]), "r"(a[2]), "r"(a[3]), "r"(b0), "r"(b1));
}

__device__ __forceinline__ void ldsm4(uint32_t* r, uint32_t addr) {
  asm volatile("ldmatrix.sync.aligned.m8n8.x4.shared.b16 {%0,%1,%2,%3}, [%4];"
               : "=r"(r[0]), "=r"(r[1]), "=r"(r[2]), "=r"(r[3]) : "r"(addr));
}

__device__ __forceinline__ void cpasync16(uint32_t saddr, const void* gptr) {
  asm volatile("cp.async.ca.shared.global [%0], [%1], 16;" :: "r"(saddr), "l"(gptr));
}

__device__ __forceinline__ void split2(float x0, float x1, uint32_t& hi, uint32_t& lo) {
  __nv_bfloat162 H = __floats2bfloat162_rn(x0, x1);
  float l0 = x0 - __bfloat162float(H.x);
  float l1 = x1 - __bfloat162float(H.y);
  __nv_bfloat162 L = __floats2bfloat162_rn(l0, l1);
  hi = *reinterpret_cast<uint32_t*>(&H);
  lo = *reinterpret_cast<uint32_t*>(&L);
}

#define WSM_BYTES 32768
#define ASM_BYTES 16384

#define LOAD_FRAGS(st, kc)                                              \
  {                                                                     \
    uint32_t aoff = (uint32_t)((((kc) + achoff) ^ aswz) << 4);          \
    uint32_t boff = (uint32_t)((((kc) + bchoff) ^ bswz) << 4);          \
    ldsm4(ah[st][0], arowaddr[0] + aoff);                               \
    ldsm4(ah[st][1], arowaddr[1] + aoff);                               \
    ldsm4(al[st][0], arowaddr[0] + aoff + ASM_BYTES);                   \
    ldsm4(al[st][1], arowaddr[1] + aoff + ASM_BYTES);                   \
    ldsm4(bh[st][0], browaddr[0] + boff);                               \
    ldsm4(bh[st][1], browaddr[1] + boff);                               \
    ldsm4(bl[st][0], browaddr[0] + boff + WSM_BYTES);                   \
    ldsm4(bl[st][1], browaddr[1] + boff + WSM_BYTES);                   \
  }

#define MMA_PASSES(st)                                                          \
  {                                                                             \
    _Pragma("unroll") for (int p = 0; p < 2; p++)                               \
        _Pragma("unroll") for (int mt = 0; mt < 2; mt++) {                      \
      mma_bf16(acc[mt * 4 + p * 2], ah[st][mt], bh[st][p][0], bh[st][p][1]);    \
      mma_bf16(acc[mt * 4 + p * 2 + 1], ah[st][mt], bh[st][p][2], bh[st][p][3]);\
    }                                                                           \
    _Pragma("unroll") for (int p = 0; p < 2; p++)                               \
        _Pragma("unroll") for (int mt = 0; mt < 2; mt++) {                      \
      mma_bf16(acc[mt * 4 + p * 2], al[st][mt], bh[st][p][0], bh[st][p][1]);    \
      mma_bf16(acc[mt * 4 + p * 2 + 1], al[st][mt], bh[st][p][2], bh[st][p][3]);\
    }                                                                           \
    _Pragma("unroll") for (int p = 0; p < 2; p++)                               \
        _Pragma("unroll") for (int mt = 0; mt < 2; mt++) {                      \
      mma_bf16(acc[mt * 4 + p * 2], ah[st][mt], bl[st][p][0], bl[st][p][1]);    \
      mma_bf16(acc[mt * 4 + p * 2 + 1], ah[st][mt], bl[st][p][2], bl[st][p][3]);\
    }                                                                           \
  }

template <int LAYER>
__global__ __launch_bounds__(256, 2) void gemm_kernel(const float* __restrict__ bias,
                                                      float* __restrict__ out_param) {
  extern __shared__ char sm[];
  char* WhS = sm;                         // [0,32K) W hi, [32K,64K) W lo
  char* AhS = sm + 2 * WSM_BYTES;         // [64K,80K) A hi, [80K,96K) A lo
  float* biasS = reinterpret_cast<float*>(sm + 2 * WSM_BYTES + 2 * ASM_BYTES);  // 128
  float* ssum = biasS + 128;              // 2*128
  float* ssq = ssum + 256;                // 2*128

  const float* A = (LAYER == 1) ? g_h : g_y1;
  float* out = (LAYER == 1) ? g_y1 : out_param;
  const __nv_bfloat16* GWh = g_Wh + (LAYER - 1) * KD * KD;
  const __nv_bfloat16* GWl = g_Wl + (LAYER - 1) * KD * KD;

  int t = threadIdx.x;
  int w = t >> 5, lane = t & 31;
  uint32_t wbase = (uint32_t)__cvta_generic_to_shared(WhS);

  if (t < 128) biasS[t] = bias[t];

  // ---- stage W hi/lo ONCE via cp.async: row r, 16B chunk c -> chunk c^(r&7) ----
  for (int idx = t; idx < 2048; idx += 256) {
    int r = idx >> 4, c = idx & 15;
    uint32_t db = (uint32_t)(r * 256 + ((c ^ (r & 7)) << 4));
    cpasync16(wbase + db, GWh + idx * 8);
    cpasync16(wbase + WSM_BYTES + db, GWl + idx * 8);
  }
  asm volatile("cp.async.commit_group;");

  // thread-invariant geometry
  int rq = lane >> 2;          // 0..7 (epilogue)
  int kq2 = (lane & 3) << 1;   // 0,2,4,6 (epilogue)
  int rb = (w >> 2) * 32;      // 2 row groups of 32
  int cb = (w & 3) * 32;       // 4 col groups of 32
  int n_lane = (lane & 7) + ((lane >> 4) << 3);
  int bchoff = (lane >> 3) & 1;
  int bswz = n_lane & 7;
  uint32_t browaddr[2];
#pragma unroll
  for (int p = 0; p < 2; p++) browaddr[p] = wbase + (cb + p * 16 + n_lane) * 256;
  int a15 = lane & 15, achoff = lane >> 4, aswz = lane & 7;
  uint32_t abase = (uint32_t)__cvta_generic_to_shared(AhS);
  uint32_t arowaddr[2];
#pragma unroll
  for (int mt = 0; mt < 2; mt++) arowaddr[mt] = abase + (rb + mt * 16 + a15) * 256;

  // ---- persistent tile loop ----
  for (int tile = blockIdx.x; tile < NBLK_G; tile += GRID_G) {
    int row0 = tile * 64;
    __syncthreads();  // planes free (prev compute done)

    // stage A (64x128 fp32), coalesced; split to bf16 hi/lo planes (same swizzle)
    for (int idx = t; idx < 2048; idx += 256) {
      int r = idx >> 5, c4 = idx & 31;
      int grow = row0 + r;
      float4 v = make_float4(0.f, 0.f, 0.f, 0.f);
      if (grow < KNT) v = *reinterpret_cast<const float4*>(A + (size_t)grow * 128 + c4 * 4);
      if (LAYER == 2) {
        int c = c4 * 4;
        v.x = fmaxf(fmaf(__ldg(&g_scale[c + 0]), v.x, __ldg(&g_shift[c + 0])), 0.f);
        v.y = fmaxf(fmaf(__ldg(&g_scale[c + 1]), v.y, __ldg(&g_shift[c + 1])), 0.f);
        v.z = fmaxf(fmaf(__ldg(&g_scale[c + 2]), v.z, __ldg(&g_shift[c + 2])), 0.f);
        v.w = fmaxf(fmaf(__ldg(&g_scale[c + 3]), v.w, __ldg(&g_shift[c + 3])), 0.f);
      }
      uint32_t h0, l0, h1, l1;
      split2(v.x, v.y, h0, l0);
      split2(v.z, v.w, h1, l1);
      int chunk = c4 >> 1, sub = (c4 & 1) << 3;
      int db = r * 256 + ((chunk ^ (r & 7)) << 4) + sub;
      *reinterpret_cast<uint2*>(AhS + db) = make_uint2(h0, h1);
      *reinterpret_cast<uint2*>(AhS + ASM_BYTES + db) = make_uint2(l0, l1);
    }
    asm volatile("cp.async.wait_group 0;");  // W resident (no-op after tile 0)
    __syncthreads();

    float acc[8][4];  // [mt*4 + p*2 + j]
#pragma unroll
    for (int i = 0; i < 8; i++)
#pragma unroll
      for (int j = 0; j < 4; j++) acc[i][j] = 0.f;

    uint32_t ah[2][2][4], al[2][2][4], bh[2][2][4], bl[2][2][4];
    LOAD_FRAGS(0, 0);
#pragma unroll
    for (int ks = 0; ks < 8; ks++) {
      const int cur = ks & 1;
      const int nxt = cur ^ 1;
      if (ks < 7) LOAD_FRAGS(nxt, 2 * (ks + 1));
      MMA_PASSES(cur);
    }

    // epilogue: store + deterministic per-tile BN partial stats
    int r0 = row0 + rb + rq;
    int r1 = r0 + 16;
    bool ok0 = r0 < KNT, ok1 = (r0 + 8) < KNT, ok2 = r1 < KNT, ok3 = (r1 + 8) < KNT;
#pragma unroll
    for (int nt = 0; nt < 4; nt++) {
      int col = cb + nt * 8 + kq2;
      float bc0 = biasS[col], bc1 = biasS[col + 1];
      float s0 = 0.f, s1 = 0.f, q0 = 0.f, q1 = 0.f;
#pragma unroll
      for (int mt = 0; mt < 2; mt++) {
        int rA = row0 + rb + mt * 16 + rq;
        bool va = mt ? ok2 : ok0;
        bool vb = mt ? ok3 : ok1;
        float* ap = acc[mt * 4 + nt];
        float y00 = ap[0] + bc0, y01 = ap[1] + bc1;
        float y10 = ap[2] + bc0, y11 = ap[3] + bc1;
        if (va) *reinterpret_cast<float2*>(out + (size_t)rA * 128 + col) = make_float2(y00, y01);
        if (vb) *reinterpret_cast<float2*>(out + (size_t)(rA + 8) * 128 + col) = make_float2(y10, y11);
        s0 += (va ? y00 : 0.f) + (vb ? y10 : 0.f);
        s1 += (va ? y01 : 0.f) + (vb ? y11 : 0.f);
        q0 += (va ? y00 * y00 : 0.f) + (vb ? y10 * y10 : 0.f);
        q1 += (va ? y01 * y01 : 0.f) + (vb ? y11 * y11 : 0.f);
      }
#pragma unroll
      for (int o = 16; o >= 4; o >>= 1) {
        s0 += __shfl_xor_sync(0xffffffffu, s0, o);
        s1 += __shfl_xor_sync(0xffffffffu, s1, o);
        q0 += __shfl_xor_sync(0xffffffffu, q0, o);
        q1 += __shfl_xor_sync(0xffffffffu, q1, o);
      }
      if (rq == 0) {
        int wp = w >> 2;
        ssum[wp * 128 + col] = s0;
        ssum[wp * 128 + col + 1] = s1;
        ssq[wp * 128 + col] = q0;
        ssq[wp * 128 + col + 1] = q1;
      }
    }
    __syncthreads();
    if (t < 128) {
      g_psum[tile * 128 + t] = ssum[t] + ssum[128 + t];
      g_psq[tile * 128 + t] = ssq[t] + ssq[128 + t];
    }
  }
}

// ---------------- reduce partials + BN params (deterministic fixed order) ----------
__global__ void redparams_kernel(const float* __restrict__ gamma,
                                 const float* __restrict__ beta, int which) {
  __shared__ float ssum[8 * 128], ssq[8 * 128];
  int t = threadIdx.x;  // 1024
  int col = t & 127, sl = t >> 7;
  int b0 = sl * 98, b1 = b0 + 98;
  if (b1 > NBLK_G) b1 = NBLK_G;
  float s = 0.f, q = 0.f;
  for (int b = b0; b < b1; b++) {
    s += g_psum[b * 128 + col];
    q += g_psq[b * 128 + col];
  }
  ssum[sl * 128 + col] = s;
  ssq[sl * 128 + col] = q;
  __syncthreads();
  if (t < 128) {
    float S = 0.f, Q = 0.f;
#pragma unroll
    for (int j = 0; j < 8; j++) {
      S += ssum[j * 128 + t];
      Q += ssq[j * 128 + t];
    }
    float inv = 1.0f / (float)KNT;
    float mu = S * inv;
    float var = Q * inv - mu * mu;
    float r = rsqrtf(var + BN_EPS);
    float sc = gamma[t] * r;
    g_scale[which * 128 + t] = sc;
    g_shift[which * 128 + t] = beta[t] - mu * sc;
  }
}

__global__ void finalize_kernel(float* __restrict__ out) {
  int i = blockIdx.x * blockDim.x + threadIdx.x;
  if (i >= KNT * 32) return;
  int c = (i & 31) << 2;
  float4 v = reinterpret_cast<float4*>(out)[i];
  v.x = fmaxf(fmaf(g_scale[128 + c + 0], v.x, g_shift[128 + c + 0]), 0.f);
  v.y = fmaxf(fmaf(g_scale[128 + c + 1], v.y, g_shift[128 + c + 1]), 0.f);
  v.z = fmaxf(fmaf(g_scale[128 + c + 2], v.z, g_shift[128 + c + 2]), 0.f);
  v.w = fmaxf(fmaf(g_scale[128 + c + 3], v.w, g_shift[128 + c + 3]), 0.f);
  reinterpret_cast<float4*>(out)[i] = v;
}

// ---------------- launch ----------------
extern "C" void kernel_launch(void* const* d_in, const int* in_sizes, int n_in,
                              void* d_out, int out_size) {
  const float* x_s = (const float*)d_in[0];
  const float* x_t = (const float*)d_in[1];
  const int* src = (const int*)d_in[2];  // int32 (JAX x64 disabled)
  const int* dst = (const int*)d_in[3];
  const float* eps = (const float*)d_in[4];
  const float* W1 = (const float*)d_in[5];
  const float* b1 = (const float*)d_in[6];
  const float* g1 = (const float*)d_in[7];
  const float* be1 = (const float*)d_in[8];
  const float* W2 = (const float*)d_in[9];
  const float* b2 = (const float*)d_in[10];
  const float* g2 = (const float*)d_in[11];
  const float* be2 = (const float*)d_in[12];
  float* out = (float*)d_out;

  const int SMEM = 2 * WSM_BYTES + 2 * ASM_BYTES + (128 + 512) * 4;  // 100928 B
  cudaFuncSetAttribute(gemm_kernel<1>, cudaFuncAttributeMaxDynamicSharedMemorySize, SMEM);
  cudaFuncSetAttribute(gemm_kernel<2>, cudaFuncAttributeMaxDynamicSharedMemorySize, SMEM);

  splitw_kernel<<<32, 256>>>(W1, W2);                                // #1 (resets g_bar)
  build_kernel<<<NBLK_B, 512>>>(src, dst);                           // #2 zero+hist+scan+scatter
  aggregate_kernel<<<(KNT * 32 + 255) / 256, 256>>>(x_s, x_t, eps);  // #3
  gemm_kernel<1><<<GRID_G, 256, SMEM>>>(b1, nullptr);                // #4 (profiled slot)
  redparams_kernel<<<1, 1024>>>(g1, be1, 0);                         // #5
  gemm_kernel<2><<<GRID_G, 256, SMEM>>>(b2, out);                    // #6
  redparams_kernel<<<1, 1024>>>(g2, be2, 1);                         // #7
  finalize_kernel<<<(KNT * 32 + 255) / 256, 256>>>(out);             // #8
}

// round 12
// speedup vs baseline: 1.3420x; 1.1239x over previous
#include <cuda_runtime.h>
#include <cuda_bf16.h>
#include <stdint.h>

#define KNS 100000
#define KNT 50000
#define KE  600000
#define KD  128
#define BN_EPS 1e-5f
#define NBLK_G 782     // ceil(KNT/64) row tiles
#define GRID_G 296     // persistent gemm blocks (2/SM)
#define NBLK_B 98      // builder blocks (resident)

// ---------------- scratch (static device memory; no allocations) ----------------
__device__ float g_h[KNT * KD];
__device__ float g_y1[KNT * KD];
__device__ int   g_counts[KNT];
__device__ int   g_offsets[KNT + 1];
__device__ int   g_cursor[KNT];
__device__ int   g_srcs[KE];
__device__ float g_psum[NBLK_G * KD];
__device__ float g_psq[NBLK_G * KD];
__device__ __align__(128) float g_scale[2 * KD];
__device__ __align__(128) float g_shift[2 * KD];
__device__ int   g_bsum[128];
__device__ unsigned g_bar;
__device__ unsigned g_bar2;
__device__ __align__(16) __nv_bfloat16 g_Wh[2 * KD * KD];
__device__ __align__(16) __nv_bfloat16 g_Wl[2 * KD * KD];

// ---------------- device-wide barriers (co-resident grids only) -------------------
__device__ __forceinline__ void gridbar(unsigned target) {
  __syncthreads();
  if (threadIdx.x == 0) {
    __threadfence();
    atomicAdd(&g_bar, 1u);
    while (*((volatile unsigned*)&g_bar) < target) {}
  }
  __syncthreads();
}

__device__ __forceinline__ void megabar(unsigned target) {
  __syncthreads();
  if (threadIdx.x == 0) {
    __threadfence();
    atomicAdd(&g_bar2, 1u);
    while (*((volatile unsigned*)&g_bar2) < target) {}
  }
  __syncthreads();
}

// ---------------- precompute hi/lo bf16 split of weights; reset barriers ----------
__global__ void splitw_kernel(const float* __restrict__ W1,
                              const float* __restrict__ W2) {
  int i = blockIdx.x * 256 + threadIdx.x;  // 0..8191, 4 elems each
  if (i == 0) { g_bar = 0; g_bar2 = 0; }
  if (i >= 8192) return;
  const float* W = (i < 4096) ? W1 : W2;
  int local = (i < 4096) ? i : (i - 4096);
  float4 v = *reinterpret_cast<const float4*>(W + local * 4);
  float arr[4] = {v.x, v.y, v.z, v.w};
  int o = i * 4;
#pragma unroll
  for (int j = 0; j < 4; j++) {
    __nv_bfloat16 h = __float2bfloat16_rn(arr[j]);
    g_Wh[o + j] = h;
    g_Wl[o + j] = __float2bfloat16_rn(arr[j] - __bfloat162float(h));
  }
}

__device__ __forceinline__ int warp_incl_scan(int x, int lane) {
#pragma unroll
  for (int o = 1; o < 32; o <<= 1) {
    int y = __shfl_up_sync(0xffffffffu, x, o);
    if (lane >= o) x += y;
  }
  return x;
}

// ------- builder: zero + histogram + exclusive scan + scatter in ONE kernel -------
__global__ void build_kernel(const int* __restrict__ src, const int* __restrict__ dst) {
  __shared__ int ws[16];
  __shared__ int sbase;
  int t = threadIdx.x, b = blockIdx.x;
  int i = b * 512 + t;
  int lane = t & 31, w = t >> 5;

  if (i < KNT) g_counts[i] = 0;
  gridbar(NBLK_B);

  const int4* dst4 = reinterpret_cast<const int4*>(dst);
  for (int e = i; e < KE / 4; e += NBLK_B * 512) {
    int4 d = dst4[e];
    atomicAdd(&g_counts[d.x], 1);
    atomicAdd(&g_counts[d.y], 1);
    atomicAdd(&g_counts[d.z], 1);
    atomicAdd(&g_counts[d.w], 1);
  }
  gridbar(2 * NBLK_B);

  int v = (i < KNT) ? __ldcg(&g_counts[i]) : 0;
  int x = warp_incl_scan(v, lane);
  if (lane == 31) ws[w] = x;
  __syncthreads();
  if (t < 16) {
    int y = ws[t];
#pragma unroll
    for (int o = 1; o < 16; o <<= 1) {
      int z = __shfl_up_sync(0xffffu, y, o);
      if (t >= o) y += z;
    }
    ws[t] = y;
  }
  __syncthreads();
  int incl = x + (w > 0 ? ws[w - 1] : 0);
  int ex = incl - v;
  if (t == 511) g_bsum[b] = incl;
  gridbar(3 * NBLK_B);

  int contrib = (t < b) ? __ldcg(&g_bsum[t]) : 0;
#pragma unroll
  for (int o = 16; o; o >>= 1) contrib += __shfl_down_sync(0xffffffffu, contrib, o);
  if (lane == 0) ws[w] = contrib;
  __syncthreads();
  if (t == 0) {
    int s = 0;
#pragma unroll
    for (int j = 0; j < 16; j++) s += ws[j];
    sbase = s;
  }
  __syncthreads();
  int off = ex + sbase;
  if (i < KNT) {
    g_offsets[i] = off;
    g_cursor[i] = off;
  }
  if (b == 0 && t == 0) g_offsets[KNT] = KE;
  gridbar(4 * NBLK_B);

  const int4* src4 = reinterpret_cast<const int4*>(src);
  for (int e = i; e < KE / 4; e += NBLK_B * 512) {
    int4 s = src4[e];
    int4 d = dst4[e];
    g_srcs[atomicAdd(&g_cursor[d.x], 1)] = s.x;
    g_srcs[atomicAdd(&g_cursor[d.y], 1)] = s.y;
    g_srcs[atomicAdd(&g_cursor[d.z], 1)] = s.z;
    g_srcs[atomicAdd(&g_cursor[d.w], 1)] = s.w;
  }
}

// ---------------- aggregation: one warp per target, high occupancy ----------------
__global__ __launch_bounds__(256, 6) void aggregate_kernel(const float* __restrict__ xs,
                                                           const float* __restrict__ xt,
                                                           const float* __restrict__ eps) {
  int gw = (blockIdx.x * blockDim.x + threadIdx.x) >> 5;
  int lane = threadIdx.x & 31;
  if (gw >= KNT) return;
  float sc = 1.0f + eps[0];
  const float4* xs4 = reinterpret_cast<const float4*>(xs);
  float4 a = reinterpret_cast<const float4*>(xt)[(size_t)gw * 32 + lane];
  a.x *= sc; a.y *= sc; a.z *= sc; a.w *= sc;
  float4 a1 = make_float4(0.f, 0.f, 0.f, 0.f);
  float4 a2 = make_float4(0.f, 0.f, 0.f, 0.f);
  float4 a3 = make_float4(0.f, 0.f, 0.f, 0.f);
  int beg = g_offsets[gw], end = g_offsets[gw + 1];
  int i = beg;
  for (; i + 3 < end; i += 4) {
    int s0 = g_srcs[i], s1 = g_srcs[i + 1], s2 = g_srcs[i + 2], s3 = g_srcs[i + 3];
    float4 v0 = xs4[(size_t)s0 * 32 + lane];
    float4 v1 = xs4[(size_t)s1 * 32 + lane];
    float4 v2 = xs4[(size_t)s2 * 32 + lane];
    float4 v3 = xs4[(size_t)s3 * 32 + lane];
    a.x += v0.x;  a.y += v0.y;  a.z += v0.z;  a.w += v0.w;
    a1.x += v1.x; a1.y += v1.y; a1.z += v1.z; a1.w += v1.w;
    a2.x += v2.x; a2.y += v2.y; a2.z += v2.z; a2.w += v2.w;
    a3.x += v3.x; a3.y += v3.y; a3.z += v3.z; a3.w += v3.w;
  }
  for (; i < end; i++) {
    float4 v0 = xs4[(size_t)g_srcs[i] * 32 + lane];
    a.x += v0.x; a.y += v0.y; a.z += v0.z; a.w += v0.w;
  }
  a.x += a1.x + a2.x + a3.x;
  a.y += a1.y + a2.y + a3.y;
  a.z += a1.z + a2.z + a3.z;
  a.w += a1.w + a2.w + a3.w;
  reinterpret_cast<float4*>(g_h)[(size_t)gw * 32 + lane] = a;
}

// ------- persistent mega kernel: gemm1 + bn1 + gemm2 + bn2 + finalize -------------
__device__ __forceinline__ void mma_bf16(float* c, const uint32_t* a,
                                         uint32_t b0, uint32_t b1) {
  asm volatile(
      "mma.sync.aligned.m16n8k16.row.col.f32.bf16.bf16.f32 "
      "{%0,%1,%2,%3}, {%4,%5,%6,%7}, {%8,%9}, {%0,%1,%2,%3};\n"
      : "+f"(c[0]), "+f"(c[1]), "+f"(c[2]), "+f"(c[3])
      : "r"(a[0]), "r"(a[1]), "r"(a[2]), "r"(a[3]), "r"(b0), "r"(b1));
}

__device__ __forceinline__ void ldsm4(uint32_t* r, uint32_t addr) {
  asm volatile("ldmatrix.sync.aligned.m8n8.x4.shared.b16 {%0,%1,%2,%3}, [%4];"
               : "=r"(r[0]), "=r"(r[1]), "=r"(r[2]), "=r"(r[3]) : "r"(addr));
}

__device__ __forceinline__ void cpasync16(uint32_t saddr, const void* gptr) {
  asm volatile("cp.async.ca.shared.global [%0], [%1], 16;" :: "r"(saddr), "l"(gptr));
}

__device__ __forceinline__ void split2(float x0, float x1, uint32_t& hi, uint32_t& lo) {
  __nv_bfloat162 H = __floats2bfloat162_rn(x0, x1);
  float l0 = x0 - __bfloat162float(H.x);
  float l1 = x1 - __bfloat162float(H.y);
  __nv_bfloat162 L = __floats2bfloat162_rn(l0, l1);
  hi = *reinterpret_cast<uint32_t*>(&H);
  lo = *reinterpret_cast<uint32_t*>(&L);
}

#define WSM_BYTES 32768
#define ASM_BYTES 16384

#define LOAD_FRAGS(st, kc)                                              \
  {                                                                     \
    uint32_t aoff = (uint32_t)((((kc) + achoff) ^ aswz) << 4);          \
    uint32_t boff = (uint32_t)((((kc) + bchoff) ^ bswz) << 4);          \
    ldsm4(ah[st][0], arowaddr[0] + aoff);                               \
    ldsm4(ah[st][1], arowaddr[1] + aoff);                               \
    ldsm4(al[st][0], arowaddr[0] + aoff + ASM_BYTES);                   \
    ldsm4(al[st][1], arowaddr[1] + aoff + ASM_BYTES);                   \
    ldsm4(bh[st][0], browaddr[0] + boff);                               \
    ldsm4(bh[st][1], browaddr[1] + boff);                               \
    ldsm4(bl[st][0], browaddr[0] + boff + WSM_BYTES);                   \
    ldsm4(bl[st][1], browaddr[1] + boff + WSM_BYTES);                   \
  }

#define MMA_PASSES(st)                                                          \
  {                                                                             \
    _Pragma("unroll") for (int p = 0; p < 2; p++)                               \
        _Pragma("unroll") for (int mt = 0; mt < 2; mt++) {                      \
      mma_bf16(acc[mt * 4 + p * 2], ah[st][mt], bh[st][p][0], bh[st][p][1]);    \
      mma_bf16(acc[mt * 4 + p * 2 + 1], ah[st][mt], bh[st][p][2], bh[st][p][3]);\
    }                                                                           \
    _Pragma("unroll") for (int p = 0; p < 2; p++)                               \
        _Pragma("unroll") for (int mt = 0; mt < 2; mt++) {                      \
      mma_bf16(acc[mt * 4 + p * 2], al[st][mt], bh[st][p][0], bh[st][p][1]);    \
      mma_bf16(acc[mt * 4 + p * 2 + 1], al[st][mt], bh[st][p][2], bh[st][p][3]);\
    }                                                                           \
    _Pragma("unroll") for (int p = 0; p < 2; p++)                               \
        _Pragma("unroll") for (int mt = 0; mt < 2; mt++) {                      \
      mma_bf16(acc[mt * 4 + p * 2], ah[st][mt], bl[st][p][0], bl[st][p][1]);    \
      mma_bf16(acc[mt * 4 + p * 2 + 1], ah[st][mt], bl[st][p][2], bl[st][p][3]);\
    }                                                                           \
  }

template <int LAYER>
__device__ __forceinline__ void gemm_layer(char* sm, const float* __restrict__ bias,
                                           float* __restrict__ out) {
  char* WhS = sm;                         // [0,32K) W hi, [32K,64K) W lo
  char* AhS = sm + 2 * WSM_BYTES;         // [64K,80K) A hi, [80K,96K) A lo
  float* biasS = reinterpret_cast<float*>(sm + 2 * WSM_BYTES + 2 * ASM_BYTES);  // 128
  float* ssum = biasS + 128;              // 2*128
  float* ssq = ssum + 256;                // 2*128

  const float* A = (LAYER == 1) ? g_h : g_y1;
  const __nv_bfloat16* GWh = g_Wh + (LAYER - 1) * KD * KD;
  const __nv_bfloat16* GWl = g_Wl + (LAYER - 1) * KD * KD;

  int t = threadIdx.x;
  int w = t >> 5, lane = t & 31;
  uint32_t wbase = (uint32_t)__cvta_generic_to_shared(WhS);

  if (t < 128) biasS[t] = bias[t];

  // ---- stage W hi/lo ONCE via cp.async: row r, 16B chunk c -> chunk c^(r&7) ----
  for (int idx = t; idx < 2048; idx += 256) {
    int r = idx >> 4, c = idx & 15;
    uint32_t db = (uint32_t)(r * 256 + ((c ^ (r & 7)) << 4));
    cpasync16(wbase + db, GWh + idx * 8);
    cpasync16(wbase + WSM_BYTES + db, GWl + idx * 8);
  }
  asm volatile("cp.async.commit_group;");

  // thread-invariant geometry
  int rq = lane >> 2;          // 0..7 (epilogue)
  int kq2 = (lane & 3) << 1;   // 0,2,4,6 (epilogue)
  int rb = (w >> 2) * 32;      // 2 row groups of 32
  int cb = (w & 3) * 32;       // 4 col groups of 32
  int n_lane = (lane & 7) + ((lane >> 4) << 3);
  int bchoff = (lane >> 3) & 1;
  int bswz = n_lane & 7;
  uint32_t browaddr[2];
#pragma unroll
  for (int p = 0; p < 2; p++) browaddr[p] = wbase + (cb + p * 16 + n_lane) * 256;
  int a15 = lane & 15, achoff = lane >> 4, aswz = lane & 7;
  uint32_t abase = (uint32_t)__cvta_generic_to_shared(AhS);
  uint32_t arowaddr[2];
#pragma unroll
  for (int mt = 0; mt < 2; mt++) arowaddr[mt] = abase + (rb + mt * 16 + a15) * 256;

  // ---- persistent tile loop ----
  for (int tile = blockIdx.x; tile < NBLK_G; tile += GRID_G) {
    int row0 = tile * 64;
    __syncthreads();  // planes free (prev compute done)

    // stage A (64x128 fp32), coalesced; split to bf16 hi/lo planes (same swizzle)
    for (int idx = t; idx < 2048; idx += 256) {
      int r = idx >> 5, c4 = idx & 31;
      int grow = row0 + r;
      float4 v = make_float4(0.f, 0.f, 0.f, 0.f);
      if (grow < KNT) v = *reinterpret_cast<const float4*>(A + (size_t)grow * 128 + c4 * 4);
      if (LAYER == 2) {
        int c = c4 * 4;
        v.x = fmaxf(fmaf(__ldcg(&g_scale[c + 0]), v.x, __ldcg(&g_shift[c + 0])), 0.f);
        v.y = fmaxf(fmaf(__ldcg(&g_scale[c + 1]), v.y, __ldcg(&g_shift[c + 1])), 0.f);
        v.z = fmaxf(fmaf(__ldcg(&g_scale[c + 2]), v.z, __ldcg(&g_shift[c + 2])), 0.f);
        v.w = fmaxf(fmaf(__ldcg(&g_scale[c + 3]), v.w, __ldcg(&g_shift[c + 3])), 0.f);
      }
      uint32_t h0, l0, h1, l1;
      split2(v.x, v.y, h0, l0);
      split2(v.z, v.w, h1, l1);
      int chunk = c4 >> 1, sub = (c4 & 1) << 3;
      int db = r * 256 + ((chunk ^ (r & 7)) << 4) + sub;
      *reinterpret_cast<uint2*>(AhS + db) = make_uint2(h0, h1);
      *reinterpret_cast<uint2*>(AhS + ASM_BYTES + db) = make_uint2(l0, l1);
    }
    asm volatile("cp.async.wait_group 0;");  // W resident (no-op after tile 0)
    __syncthreads();

    float acc[8][4];  // [mt*4 + p*2 + j]
#pragma unroll
    for (int i = 0; i < 8; i++)
#pragma unroll
      for (int j = 0; j < 4; j++) acc[i][j] = 0.f;

    uint32_t ah[2][2][4], al[2][2][4], bh[2][2][4], bl[2][2][4];
    LOAD_FRAGS(0, 0);
#pragma unroll
    for (int ks = 0; ks < 8; ks++) {
      const int cur = ks & 1;
      const int nxt = cur ^ 1;
      if (ks < 7) LOAD_FRAGS(nxt, 2 * (ks + 1));
      MMA_PASSES(cur);
    }

    // epilogue: store + deterministic per-tile BN partial stats
    int r0 = row0 + rb + rq;
    int r1 = r0 + 16;
    bool ok0 = r0 < KNT, ok1 = (r0 + 8) < KNT, ok2 = r1 < KNT, ok3 = (r1 + 8) < KNT;
#pragma unroll
    for (int nt = 0; nt < 4; nt++) {
      int col = cb + nt * 8 + kq2;
      float bc0 = biasS[col], bc1 = biasS[col + 1];
      float s0 = 0.f, s1 = 0.f, q0 = 0.f, q1 = 0.f;
#pragma unroll
      for (int mt = 0; mt < 2; mt++) {
        int rA = row0 + rb + mt * 16 + rq;
        bool va = mt ? ok2 : ok0;
        bool vb = mt ? ok3 : ok1;
        float* ap = acc[mt * 4 + nt];
        float y00 = ap[0] + bc0, y01 = ap[1] + bc1;
        float y10 = ap[2] + bc0, y11 = ap[3] + bc1;
        if (va) *reinterpret_cast<float2*>(out + (size_t)rA * 128 + col) = make_float2(y00, y01);
        if (vb) *reinterpret_cast<float2*>(out + (size_t)(rA + 8) * 128 + col) = make_float2(y10, y11);
        s0 += (va ? y00 : 0.f) + (vb ? y10 : 0.f);
        s1 += (va ? y01 : 0.f) + (vb ? y11 : 0.f);
        q0 += (va ? y00 * y00 : 0.f) + (vb ? y10 * y10 : 0.f);
        q1 += (va ? y01 * y01 : 0.f) + (vb ? y11 * y11 : 0.f);
      }
#pragma unroll
      for (int o = 16; o >= 4; o >>= 1) {
        s0 += __shfl_xor_sync(0xffffffffu, s0, o);
        s1 += __shfl_xor_sync(0xffffffffu, s1, o);
        q0 += __shfl_xor_sync(0xffffffffu, q0, o);
        q1 += __shfl_xor_sync(0xffffffffu, q1, o);
      }
      if (rq == 0) {
        int wp = w >> 2;
        ssum[wp * 128 + col] = s0;
        ssum[wp * 128 + col + 1] = s1;
        ssq[wp * 128 + col] = q0;
        ssq[wp * 128 + col + 1] = q1;
      }
    }
    __syncthreads();
    if (t < 128) {
      g_psum[tile * 128 + t] = ssum[t] + ssum[128 + t];
      g_psq[tile * 128 + t] = ssq[t] + ssq[128 + t];
    }
  }
}

// in-kernel BN params: block col (<128) reduces its column (deterministic tree)
__device__ __forceinline__ void redparams_inline(char* sm, int which,
                                                 const float* __restrict__ gamma,
                                                 const float* __restrict__ beta) {
  if (blockIdx.x >= 128) return;
  float* rs = reinterpret_cast<float*>(sm);          // 256
  float* rq = rs + 256;                              // 256
  int t = threadIdx.x;
  int col = blockIdx.x;
  float s = 0.f, q = 0.f;
  for (int b = t; b < NBLK_G; b += 256) {
    s += __ldcg(&g_psum[b * 128 + col]);
    q += __ldcg(&g_psq[b * 128 + col]);
  }
  rs[t] = s;
  rq[t] = q;
  __syncthreads();
#pragma unroll
  for (int o = 128; o; o >>= 1) {
    if (t < o) {
      rs[t] += rs[t + o];
      rq[t] += rq[t + o];
    }
    __syncthreads();
  }
  if (t == 0) {
    float inv = 1.0f / (float)KNT;
    float mu = rs[0] * inv;
    float var = rq[0] * inv - mu * mu;
    float r = rsqrtf(var + BN_EPS);
    float sc = gamma[col] * r;
    g_scale[which * 128 + col] = sc;
    g_shift[which * 128 + col] = beta[col] - mu * sc;
  }
}

__global__ __launch_bounds__(256, 2) void mega_kernel(const float* __restrict__ b1,
                                                      const float* __restrict__ g1,
                                                      const float* __restrict__ be1,
                                                      const float* __restrict__ b2,
                                                      const float* __restrict__ g2,
                                                      const float* __restrict__ be2,
                                                      float* __restrict__ out) {
  extern __shared__ char sm[];
  int t = threadIdx.x;

  gemm_layer<1>(sm, b1, g_y1);
  megabar(1 * GRID_G);
  redparams_inline(sm, 0, g1, be1);
  megabar(2 * GRID_G);
  gemm_layer<2>(sm, b2, out);
  megabar(3 * GRID_G);
  redparams_inline(sm, 1, g2, be2);
  megabar(4 * GRID_G);

  // finalize: BN2 + ReLU over output (params to smem first)
  float* scS = reinterpret_cast<float*>(sm);      // 128
  float* shS = scS + 128;                         // 128
  if (t < 128) {
    scS[t] = __ldcg(&g_scale[128 + t]);
    shS[t] = __ldcg(&g_shift[128 + t]);
  }
  __syncthreads();
  float4* out4 = reinterpret_cast<float4*>(out);
  for (int i = blockIdx.x * 256 + t; i < KNT * 32; i += GRID_G * 256) {
    int c = (i & 31) << 2;
    float4 v = out4[i];
    v.x = fmaxf(fmaf(scS[c + 0], v.x, shS[c + 0]), 0.f);
    v.y = fmaxf(fmaf(scS[c + 1], v.y, shS[c + 1]), 0.f);
    v.z = fmaxf(fmaf(scS[c + 2], v.z, shS[c + 2]), 0.f);
    v.w = fmaxf(fmaf(scS[c + 3], v.w, shS[c + 3]), 0.f);
    out4[i] = v;
  }
}

// ---------------- launch ----------------
extern "C" void kernel_launch(void* const* d_in, const int* in_sizes, int n_in,
                              void* d_out, int out_size) {
  const float* x_s = (const float*)d_in[0];
  const float* x_t = (const float*)d_in[1];
  const int* src = (const int*)d_in[2];  // int32 (JAX x64 disabled)
  const int* dst = (const int*)d_in[3];
  const float* eps = (const float*)d_in[4];
  const float* W1 = (const float*)d_in[5];
  const float* b1 = (const float*)d_in[6];
  const float* g1 = (const float*)d_in[7];
  const float* be1 = (const float*)d_in[8];
  const float* W2 = (const float*)d_in[9];
  const float* b2 = (const float*)d_in[10];
  const float* g2 = (const float*)d_in[11];
  const float* be2 = (const float*)d_in[12];
  float* out = (float*)d_out;

  const int SMEM = 2 * WSM_BYTES + 2 * ASM_BYTES + (128 + 512) * 4;  // 100928 B
  cudaFuncSetAttribute(mega_kernel, cudaFuncAttributeMaxDynamicSharedMemorySize, SMEM);

  splitw_kernel<<<32, 256>>>(W1, W2);                                // #1 (resets bars)
  build_kernel<<<NBLK_B, 512>>>(src, dst);                           // #2 zero+hist+scan+scatter
  aggregate_kernel<<<(KNT * 32 + 255) / 256, 256>>>(x_s, x_t, eps);  // #3
  mega_kernel<<<GRID_G, 256, SMEM>>>(b1, g1, be1, b2, g2, be2, out); // #4 (profiled slot)
}

// round 13
// speedup vs baseline: 1.3519x; 1.0074x over previous
#include <cuda_runtime.h>
#include <cuda_bf16.h>
#include <stdint.h>

#define KNS 100000
#define KNT 50000
#define KE  600000
#define KD  128
#define BN_EPS 1e-5f
#define NBLK_G 782     // ceil(KNT/64) row tiles
#define KNT_PAD (NBLK_G * 64)
#define GRID_G 296     // persistent gemm blocks (2/SM)
#define NBLK_B 98      // builder blocks (resident)

// ---------------- scratch (static device memory; no allocations) ----------------
__device__ float g_y1[KNT * KD];
__device__ __align__(16) __nv_bfloat16 g_Ah[KNT_PAD * KD];  // pre-swizzled hi plane
__device__ __align__(16) __nv_bfloat16 g_Al[KNT_PAD * KD];  // pre-swizzled lo plane
__device__ int   g_counts[KNT];
__device__ int   g_offsets[KNT + 1];
__device__ int   g_cursor[KNT];
__device__ int   g_srcs[KE];
__device__ float g_psum[NBLK_G * KD];
__device__ float g_psq[NBLK_G * KD];
__device__ __align__(128) float g_scale[2 * KD];
__device__ __align__(128) float g_shift[2 * KD];
__device__ int   g_bsum[128];
__device__ unsigned g_bar;
__device__ unsigned g_bar2;
__device__ __align__(16) __nv_bfloat16 g_Wh[2 * KD * KD];
__device__ __align__(16) __nv_bfloat16 g_Wl[2 * KD * KD];

// ---------------- device-wide barriers (co-resident grids only) -------------------
__device__ __forceinline__ void gridbar(unsigned target) {
  __syncthreads();
  if (threadIdx.x == 0) {
    __threadfence();
    atomicAdd(&g_bar, 1u);
    while (*((volatile unsigned*)&g_bar) < target) {}
  }
  __syncthreads();
}

__device__ __forceinline__ void megabar(unsigned target) {
  __syncthreads();
  if (threadIdx.x == 0) {
    __threadfence();
    atomicAdd(&g_bar2, 1u);
    while (*((volatile unsigned*)&g_bar2) < target) {}
  }
  __syncthreads();
}

// ---------------- precompute hi/lo bf16 split of weights; reset barriers ----------
__global__ void splitw_kernel(const float* __restrict__ W1,
                              const float* __restrict__ W2) {
  int i = blockIdx.x * 256 + threadIdx.x;  // 0..8191, 4 elems each
  if (i == 0) { g_bar = 0; g_bar2 = 0; }
  if (i >= 8192) return;
  const float* W = (i < 4096) ? W1 : W2;
  int local = (i < 4096) ? i : (i - 4096);
  float4 v = *reinterpret_cast<const float4*>(W + local * 4);
  float arr[4] = {v.x, v.y, v.z, v.w};
  int o = i * 4;
#pragma unroll
  for (int j = 0; j < 4; j++) {
    __nv_bfloat16 h = __float2bfloat16_rn(arr[j]);
    g_Wh[o + j] = h;
    g_Wl[o + j] = __float2bfloat16_rn(arr[j] - __bfloat162float(h));
  }
}

__device__ __forceinline__ int warp_incl_scan(int x, int lane) {
#pragma unroll
  for (int o = 1; o < 32; o <<= 1) {
    int y = __shfl_up_sync(0xffffffffu, x, o);
    if (lane >= o) x += y;
  }
  return x;
}

// ------- builder: zero + histogram + exclusive scan + scatter in ONE kernel -------
__global__ void build_kernel(const int* __restrict__ src, const int* __restrict__ dst) {
  __shared__ int ws[16];
  __shared__ int sbase;
  int t = threadIdx.x, b = blockIdx.x;
  int i = b * 512 + t;
  int lane = t & 31, w = t >> 5;

  if (i < KNT) g_counts[i] = 0;
  gridbar(NBLK_B);

  const int4* dst4 = reinterpret_cast<const int4*>(dst);
  for (int e = i; e < KE / 4; e += NBLK_B * 512) {
    int4 d = dst4[e];
    atomicAdd(&g_counts[d.x], 1);
    atomicAdd(&g_counts[d.y], 1);
    atomicAdd(&g_counts[d.z], 1);
    atomicAdd(&g_counts[d.w], 1);
  }
  gridbar(2 * NBLK_B);

  int v = (i < KNT) ? __ldcg(&g_counts[i]) : 0;
  int x = warp_incl_scan(v, lane);
  if (lane == 31) ws[w] = x;
  __syncthreads();
  if (t < 16) {
    int y = ws[t];
#pragma unroll
    for (int o = 1; o < 16; o <<= 1) {
      int z = __shfl_up_sync(0xffffu, y, o);
      if (t >= o) y += z;
    }
    ws[t] = y;
  }
  __syncthreads();
  int incl = x + (w > 0 ? ws[w - 1] : 0);
  int ex = incl - v;
  if (t == 511) g_bsum[b] = incl;
  gridbar(3 * NBLK_B);

  int contrib = (t < b) ? __ldcg(&g_bsum[t]) : 0;
#pragma unroll
  for (int o = 16; o; o >>= 1) contrib += __shfl_down_sync(0xffffffffu, contrib, o);
  if (lane == 0) ws[w] = contrib;
  __syncthreads();
  if (t == 0) {
    int s = 0;
#pragma unroll
    for (int j = 0; j < 16; j++) s += ws[j];
    sbase = s;
  }
  __syncthreads();
  int off = ex + sbase;
  if (i < KNT) {
    g_offsets[i] = off;
    g_cursor[i] = off;
  }
  if (b == 0 && t == 0) g_offsets[KNT] = KE;
  gridbar(4 * NBLK_B);

  const int4* src4 = reinterpret_cast<const int4*>(src);
  for (int e = i; e < KE / 4; e += NBLK_B * 512) {
    int4 s = src4[e];
    int4 d = dst4[e];
    g_srcs[atomicAdd(&g_cursor[d.x], 1)] = s.x;
    g_srcs[atomicAdd(&g_cursor[d.y], 1)] = s.y;
    g_srcs[atomicAdd(&g_cursor[d.z], 1)] = s.z;
    g_srcs[atomicAdd(&g_cursor[d.w], 1)] = s.w;
  }
}

__device__ __forceinline__ void split2(float x0, float x1, uint32_t& hi, uint32_t& lo) {
  __nv_bfloat162 H = __floats2bfloat162_rn(x0, x1);
  float l0 = x0 - __bfloat162float(H.x);
  float l1 = x1 - __bfloat162float(H.y);
  __nv_bfloat162 L = __floats2bfloat162_rn(l0, l1);
  hi = *reinterpret_cast<uint32_t*>(&H);
  lo = *reinterpret_cast<uint32_t*>(&L);
}

// ---- aggregation: one warp per target; writes pre-swizzled bf16 hi/lo planes ----
__global__ __launch_bounds__(256, 6) void aggregate_kernel(const float* __restrict__ xs,
                                                           const float* __restrict__ xt,
                                                           const float* __restrict__ eps) {
  int gw = (blockIdx.x * blockDim.x + threadIdx.x) >> 5;
  int lane = threadIdx.x & 31;
  if (gw >= KNT) return;
  float sc = 1.0f + eps[0];
  const float4* xs4 = reinterpret_cast<const float4*>(xs);
  float4 a = reinterpret_cast<const float4*>(xt)[(size_t)gw * 32 + lane];
  a.x *= sc; a.y *= sc; a.z *= sc; a.w *= sc;
  float4 a1 = make_float4(0.f, 0.f, 0.f, 0.f);
  float4 a2 = make_float4(0.f, 0.f, 0.f, 0.f);
  float4 a3 = make_float4(0.f, 0.f, 0.f, 0.f);
  int beg = g_offsets[gw], end = g_offsets[gw + 1];
  int i = beg;
  for (; i + 3 < end; i += 4) {
    int s0 = g_srcs[i], s1 = g_srcs[i + 1], s2 = g_srcs[i + 2], s3 = g_srcs[i + 3];
    float4 v0 = xs4[(size_t)s0 * 32 + lane];
    float4 v1 = xs4[(size_t)s1 * 32 + lane];
    float4 v2 = xs4[(size_t)s2 * 32 + lane];
    float4 v3 = xs4[(size_t)s3 * 32 + lane];
    a.x += v0.x;  a.y += v0.y;  a.z += v0.z;  a.w += v0.w;
    a1.x += v1.x; a1.y += v1.y; a1.z += v1.z; a1.w += v1.w;
    a2.x += v2.x; a2.y += v2.y; a2.z += v2.z; a2.w += v2.w;
    a3.x += v3.x; a3.y += v3.y; a3.z += v3.z; a3.w += v3.w;
  }
  for (; i < end; i++) {
    float4 v0 = xs4[(size_t)g_srcs[i] * 32 + lane];
    a.x += v0.x; a.y += v0.y; a.z += v0.z; a.w += v0.w;
  }
  a.x += a1.x + a2.x + a3.x;
  a.y += a1.y + a2.y + a3.y;
  a.z += a1.z + a2.z + a3.z;
  a.w += a1.w + a2.w + a3.w;
  // split to bf16 hi/lo, write pre-swizzled (swizzle depends on gw&7 only)
  uint32_t h0, l0, h1, l1;
  split2(a.x, a.y, h0, l0);
  split2(a.z, a.w, h1, l1);
  int chunk = lane >> 1, sub = (lane & 1) << 3;
  size_t db = (size_t)gw * 256 + (uint32_t)(((chunk ^ (gw & 7)) << 4) + sub);
  *reinterpret_cast<uint2*>(reinterpret_cast<char*>(g_Ah) + db) = make_uint2(h0, h1);
  *reinterpret_cast<uint2*>(reinterpret_cast<char*>(g_Al) + db) = make_uint2(l0, l1);
}

// ------- persistent mega kernel: gemm1 + bn1 + gemm2 + bn2 + finalize -------------
__device__ __forceinline__ void mma_bf16(float* c, const uint32_t* a,
                                         uint32_t b0, uint32_t b1) {
  asm volatile(
      "mma.sync.aligned.m16n8k16.row.col.f32.bf16.bf16.f32 "
      "{%0,%1,%2,%3}, {%4,%5,%6,%7}, {%8,%9}, {%0,%1,%2,%3};\n"
      : "+f"(c[0]), "+f"(c[1]), "+f"(c[2]), "+f"(c[3])
      : "r"(a[0]), "r"(a[1]), "r"(a[2]), "r"(a[3]), "r"(b0), "r"(b1));
}

__device__ __forceinline__ void ldsm4(uint32_t* r, uint32_t addr) {
  asm volatile("ldmatrix.sync.aligned.m8n8.x4.shared.b16 {%0,%1,%2,%3}, [%4];"
               : "=r"(r[0]), "=r"(r[1]), "=r"(r[2]), "=r"(r[3]) : "r"(addr));
}

__device__ __forceinline__ void cpasync16(uint32_t saddr, const void* gptr) {
  asm volatile("cp.async.ca.shared.global [%0], [%1], 16;" :: "r"(saddr), "l"(gptr));
}

#define WSM_BYTES 32768
#define ASM_BYTES 16384

#define LOAD_FRAGS(st, kc)                                              \
  {                                                                     \
    uint32_t aoff = (uint32_t)((((kc) + achoff) ^ aswz) << 4);          \
    uint32_t boff = (uint32_t)((((kc) + bchoff) ^ bswz) << 4);          \
    ldsm4(ah[st][0], arowaddr[0] + aoff);                               \
    ldsm4(ah[st][1], arowaddr[1] + aoff);                               \
    ldsm4(al[st][0], arowaddr[0] + aoff + ASM_BYTES);                   \
    ldsm4(al[st][1], arowaddr[1] + aoff + ASM_BYTES);                   \
    ldsm4(bh[st][0], browaddr[0] + boff);                               \
    ldsm4(bh[st][1], browaddr[1] + boff);                               \
    ldsm4(bl[st][0], browaddr[0] + boff + WSM_BYTES);                   \
    ldsm4(bl[st][1], browaddr[1] + boff + WSM_BYTES);                   \
  }

#define MMA_PASSES(st)                                                          \
  {                                                                             \
    _Pragma("unroll") for (int p = 0; p < 2; p++)                               \
        _Pragma("unroll") for (int mt = 0; mt < 2; mt++) {                      \
      mma_bf16(acc[mt * 4 + p * 2], ah[st][mt], bh[st][p][0], bh[st][p][1]);    \
      mma_bf16(acc[mt * 4 + p * 2 + 1], ah[st][mt], bh[st][p][2], bh[st][p][3]);\
    }                                                                           \
    _Pragma("unroll") for (int p = 0; p < 2; p++)                               \
        _Pragma("unroll") for (int mt = 0; mt < 2; mt++) {                      \
      mma_bf16(acc[mt * 4 + p * 2], al[st][mt], bh[st][p][0], bh[st][p][1]);    \
      mma_bf16(acc[mt * 4 + p * 2 + 1], al[st][mt], bh[st][p][2], bh[st][p][3]);\
    }                                                                           \
    _Pragma("unroll") for (int p = 0; p < 2; p++)                               \
        _Pragma("unroll") for (int mt = 0; mt < 2; mt++) {                      \
      mma_bf16(acc[mt * 4 + p * 2], ah[st][mt], bl[st][p][0], bl[st][p][1]);    \
      mma_bf16(acc[mt * 4 + p * 2 + 1], ah[st][mt], bl[st][p][2], bl[st][p][3]);\
    }                                                                           \
  }

// epilogue shared by both layers
#define GEMM_EPILOGUE(row0_)                                                        \
  {                                                                                 \
    int r0 = (row0_) + rb + rq;                                                     \
    int r1 = r0 + 16;                                                               \
    bool ok0 = r0 < KNT, ok1 = (r0 + 8) < KNT, ok2 = r1 < KNT, ok3 = (r1 + 8) < KNT;\
    _Pragma("unroll") for (int nt = 0; nt < 4; nt++) {                              \
      int col = cb + nt * 8 + kq2;                                                  \
      float bc0 = biasS[col], bc1 = biasS[col + 1];                                 \
      float s0 = 0.f, s1 = 0.f, q0 = 0.f, q1 = 0.f;                                 \
      _Pragma("unroll") for (int mt = 0; mt < 2; mt++) {                            \
        int rA = (row0_) + rb + mt * 16 + rq;                                       \
        bool va = mt ? ok2 : ok0;                                                   \
        bool vb = mt ? ok3 : ok1;                                                   \
        float* ap = acc[mt * 4 + nt];                                               \
        float y00 = ap[0] + bc0, y01 = ap[1] + bc1;                                 \
        float y10 = ap[2] + bc0, y11 = ap[3] + bc1;                                 \
        if (va) *reinterpret_cast<float2*>(out + (size_t)rA * 128 + col) =          \
            make_float2(y00, y01);                                                  \
        if (vb) *reinterpret_cast<float2*>(out + (size_t)(rA + 8) * 128 + col) =    \
            make_float2(y10, y11);                                                  \
        s0 += (va ? y00 : 0.f) + (vb ? y10 : 0.f);                                  \
        s1 += (va ? y01 : 0.f) + (vb ? y11 : 0.f);                                  \
        q0 += (va ? y00 * y00 : 0.f) + (vb ? y10 * y10 : 0.f);                      \
        q1 += (va ? y01 * y01 : 0.f) + (vb ? y11 * y11 : 0.f);                      \
      }                                                                             \
      _Pragma("unroll") for (int o = 16; o >= 4; o >>= 1) {                         \
        s0 += __shfl_xor_sync(0xffffffffu, s0, o);                                  \
        s1 += __shfl_xor_sync(0xffffffffu, s1, o);                                  \
        q0 += __shfl_xor_sync(0xffffffffu, q0, o);                                  \
        q1 += __shfl_xor_sync(0xffffffffu, q1, o);                                  \
      }                                                                             \
      if (rq == 0) {                                                                \
        int wp = w >> 2;                                                            \
        ssum[wp * 128 + col] = s0;                                                  \
        ssum[wp * 128 + col + 1] = s1;                                              \
        ssq[wp * 128 + col] = q0;                                                   \
        ssq[wp * 128 + col + 1] = q1;                                               \
      }                                                                             \
    }                                                                               \
  }

template <int LAYER>
__device__ __forceinline__ void gemm_layer(char* sm, const float* __restrict__ bias,
                                           float* __restrict__ out) {
  char* WhS = sm;                         // [0,32K) W hi, [32K,64K) W lo
  char* AhS = sm + 2 * WSM_BYTES;         // [64K,80K) A hi, [80K,96K) A lo
  float* biasS = reinterpret_cast<float*>(sm + 2 * WSM_BYTES + 2 * ASM_BYTES);  // 128
  float* ssum = biasS + 128;              // 2*128
  float* ssq = ssum + 256;                // 2*128

  const __nv_bfloat16* GWh = g_Wh + (LAYER - 1) * KD * KD;
  const __nv_bfloat16* GWl = g_Wl + (LAYER - 1) * KD * KD;

  int t = threadIdx.x;
  int w = t >> 5, lane = t & 31;
  uint32_t wbase = (uint32_t)__cvta_generic_to_shared(WhS);
  uint32_t abase = (uint32_t)__cvta_generic_to_shared(AhS);

  if (t < 128) biasS[t] = bias[t];

  // ---- stage W hi/lo ONCE via cp.async: row r, 16B chunk c -> chunk c^(r&7) ----
  for (int idx = t; idx < 2048; idx += 256) {
    int r = idx >> 4, c = idx & 15;
    uint32_t db = (uint32_t)(r * 256 + ((c ^ (r & 7)) << 4));
    cpasync16(wbase + db, GWh + idx * 8);
    cpasync16(wbase + WSM_BYTES + db, GWl + idx * 8);
  }
  asm volatile("cp.async.commit_group;");

  // thread-invariant geometry
  int rq = lane >> 2;          // 0..7 (epilogue)
  int kq2 = (lane & 3) << 1;   // 0,2,4,6 (epilogue)
  int rb = (w >> 2) * 32;      // 2 row groups of 32
  int cb = (w & 3) * 32;       // 4 col groups of 32
  int n_lane = (lane & 7) + ((lane >> 4) << 3);
  int bchoff = (lane >> 3) & 1;
  int bswz = n_lane & 7;
  uint32_t browaddr[2];
#pragma unroll
  for (int p = 0; p < 2; p++) browaddr[p] = wbase + (cb + p * 16 + n_lane) * 256;
  int a15 = lane & 15, achoff = lane >> 4, aswz = lane & 7;
  uint32_t arowaddr[2];
#pragma unroll
  for (int mt = 0; mt < 2; mt++) arowaddr[mt] = abase + (rb + mt * 16 + a15) * 256;

  if (LAYER == 1) {
    // --- pipelined: A tiles are pre-split pre-swizzled; staging = linear cp.async ---
    int tile0 = blockIdx.x;
    if (tile0 < NBLK_G) {
      const char* srcH = reinterpret_cast<const char*>(g_Ah) + (size_t)tile0 * 64 * 256;
      const char* srcL = reinterpret_cast<const char*>(g_Al) + (size_t)tile0 * 64 * 256;
      for (int idx = t; idx < 1024; idx += 256) {
        cpasync16(abase + idx * 16, srcH + idx * 16);
        cpasync16(abase + ASM_BYTES + idx * 16, srcL + idx * 16);
      }
      asm volatile("cp.async.commit_group;");
    }
    for (int tile = blockIdx.x; tile < NBLK_G; tile += GRID_G) {
      int row0 = tile * 64;
      asm volatile("cp.async.wait_group 0;");
      __syncthreads();

      float acc[8][4];
#pragma unroll
      for (int i = 0; i < 8; i++)
#pragma unroll
        for (int j = 0; j < 4; j++) acc[i][j] = 0.f;

      uint32_t ah[2][2][4], al[2][2][4], bh[2][2][4], bl[2][2][4];
      LOAD_FRAGS(0, 0);
#pragma unroll
      for (int ks = 0; ks < 8; ks++) {
        const int cur = ks & 1;
        const int nxt = cur ^ 1;
        if (ks < 7) LOAD_FRAGS(nxt, 2 * (ks + 1));
        MMA_PASSES(cur);
      }
      __syncthreads();  // all warps done reading A planes

      int ntile = tile + GRID_G;
      if (ntile < NBLK_G) {  // prefetch next A tile; flies during epilogue
        const char* srcH = reinterpret_cast<const char*>(g_Ah) + (size_t)ntile * 64 * 256;
        const char* srcL = reinterpret_cast<const char*>(g_Al) + (size_t)ntile * 64 * 256;
        for (int idx = t; idx < 1024; idx += 256) {
          cpasync16(abase + idx * 16, srcH + idx * 16);
          cpasync16(abase + ASM_BYTES + idx * 16, srcL + idx * 16);
        }
        asm volatile("cp.async.commit_group;");
      }

      GEMM_EPILOGUE(row0);
      __syncthreads();
      if (t < 128) {
        g_psum[tile * 128 + t] = ssum[t] + ssum[128 + t];
        g_psq[tile * 128 + t] = ssq[t] + ssq[128 + t];
      }
    }
  } else {
    // --- layer 2: fp32 y1 + BN1 + ReLU + split staged per tile ---
    for (int tile = blockIdx.x; tile < NBLK_G; tile += GRID_G) {
      int row0 = tile * 64;
      __syncthreads();  // planes free (prev compute done)

      for (int idx = t; idx < 2048; idx += 256) {
        int r = idx >> 5, c4 = idx & 31;
        int grow = row0 + r;
        float4 v = make_float4(0.f, 0.f, 0.f, 0.f);
        if (grow < KNT) v = *reinterpret_cast<const float4*>(g_y1 + (size_t)grow * 128 + c4 * 4);
        int c = c4 * 4;
        v.x = fmaxf(fmaf(__ldcg(&g_scale[c + 0]), v.x, __ldcg(&g_shift[c + 0])), 0.f);
        v.y = fmaxf(fmaf(__ldcg(&g_scale[c + 1]), v.y, __ldcg(&g_shift[c + 1])), 0.f);
        v.z = fmaxf(fmaf(__ldcg(&g_scale[c + 2]), v.z, __ldcg(&g_shift[c + 2])), 0.f);
        v.w = fmaxf(fmaf(__ldcg(&g_scale[c + 3]), v.w, __ldcg(&g_shift[c + 3])), 0.f);
        uint32_t h0, l0, h1, l1;
        split2(v.x, v.y, h0, l0);
        split2(v.z, v.w, h1, l1);
        int chunk = c4 >> 1, sub = (c4 & 1) << 3;
        int db = r * 256 + ((chunk ^ (r & 7)) << 4) + sub;
        *reinterpret_cast<uint2*>(AhS + db) = make_uint2(h0, h1);
        *reinterpret_cast<uint2*>(AhS + ASM_BYTES + db) = make_uint2(l0, l1);
      }
      asm volatile("cp.async.wait_group 0;");  // W resident (no-op after tile 0)
      __syncthreads();

      float acc[8][4];
#pragma unroll
      for (int i = 0; i < 8; i++)
#pragma unroll
        for (int j = 0; j < 4; j++) acc[i][j] = 0.f;

      uint32_t ah[2][2][4], al[2][2][4], bh[2][2][4], bl[2][2][4];
      LOAD_FRAGS(0, 0);
#pragma unroll
      for (int ks = 0; ks < 8; ks++) {
        const int cur = ks & 1;
        const int nxt = cur ^ 1;
        if (ks < 7) LOAD_FRAGS(nxt, 2 * (ks + 1));
        MMA_PASSES(cur);
      }

      GEMM_EPILOGUE(row0);
      __syncthreads();
      if (t < 128) {
        g_psum[tile * 128 + t] = ssum[t] + ssum[128 + t];
        g_psq[tile * 128 + t] = ssq[t] + ssq[128 + t];
      }
    }
  }
}

// in-kernel BN params: block col (<128) reduces its column (deterministic tree)
__device__ __forceinline__ void redparams_inline(char* sm, int which,
                                                 const float* __restrict__ gamma,
                                                 const float* __restrict__ beta) {
  if (blockIdx.x >= 128) return;
  float* rs = reinterpret_cast<float*>(sm);          // 256
  float* rq = rs + 256;                              // 256
  int t = threadIdx.x;
  int col = blockIdx.x;
  float s = 0.f, q = 0.f;
  for (int b = t; b < NBLK_G; b += 256) {
    s += __ldcg(&g_psum[b * 128 + col]);
    q += __ldcg(&g_psq[b * 128 + col]);
  }
  rs[t] = s;
  rq[t] = q;
  __syncthreads();
#pragma unroll
  for (int o = 128; o; o >>= 1) {
    if (t < o) {
      rs[t] += rs[t + o];
      rq[t] += rq[t + o];
    }
    __syncthreads();
  }
  if (t == 0) {
    float inv = 1.0f / (float)KNT;
    float mu = rs[0] * inv;
    float var = rq[0] * inv - mu * mu;
    float r = rsqrtf(var + BN_EPS);
    float sc = gamma[col] * r;
    g_scale[which * 128 + col] = sc;
    g_shift[which * 128 + col] = beta[col] - mu * sc;
  }
}

__global__ __launch_bounds__(256, 2) void mega_kernel(const float* __restrict__ b1,
                                                      const float* __restrict__ g1,
                                                      const float* __restrict__ be1,
                                                      const float* __restrict__ b2,
                                                      const float* __restrict__ g2,
                                                      const float* __restrict__ be2,
                                                      float* __restrict__ out) {
  extern __shared__ char sm[];
  int t = threadIdx.x;

  gemm_layer<1>(sm, b1, g_y1);
  megabar(1 * GRID_G);
  redparams_inline(sm, 0, g1, be1);
  megabar(2 * GRID_G);
  gemm_layer<2>(sm, b2, out);
  megabar(3 * GRID_G);
  redparams_inline(sm, 1, g2, be2);
  megabar(4 * GRID_G);

  // finalize: BN2 + ReLU over output (params to smem first)
  float* scS = reinterpret_cast<float*>(sm);      // 128
  float* shS = scS + 128;                         // 128
  if (t < 128) {
    scS[t] = __ldcg(&g_scale[128 + t]);
    shS[t] = __ldcg(&g_shift[128 + t]);
  }
  __syncthreads();
  float4* out4 = reinterpret_cast<float4*>(out);
  for (int i = blockIdx.x * 256 + t; i < KNT * 32; i += GRID_G * 256) {
    int c = (i & 31) << 2;
    float4 v = out4[i];
    v.x = fmaxf(fmaf(scS[c + 0], v.x, shS[c + 0]), 0.f);
    v.y = fmaxf(fmaf(scS[c + 1], v.y, shS[c + 1]), 0.f);
    v.z = fmaxf(fmaf(scS[c + 2], v.z, shS[c + 2]), 0.f);
    v.w = fmaxf(fmaf(scS[c + 3], v.w, shS[c + 3]), 0.f);
    out4[i] = v;
  }
}

// ---------------- launch ----------------
extern "C" void kernel_launch(void* const* d_in, const int* in_sizes, int n_in,
                              void* d_out, int out_size) {
  const float* x_s = (const float*)d_in[0];
  const float* x_t = (const float*)d_in[1];
  const int* src = (const int*)d_in[2];  // int32 (JAX x64 disabled)
  const int* dst = (const int*)d_in[3];
  const float* eps = (const float*)d_in[4];
  const float* W1 = (const float*)d_in[5];
  const float* b1 = (const float*)d_in[6];
  const float* g1 = (const float*)d_in[7];
  const float* be1 = (const float*)d_in[8];
  const float* W2 = (const float*)d_in[9];
  const float* b2 = (const float*)d_in[10];
  const float* g2 = (const float*)d_in[11];
  const float* be2 = (const float*)d_in[12];
  float* out = (float*)d_out;

  const int SMEM = 2 * WSM_BYTES + 2 * ASM_BYTES + (128 + 512) * 4;  // 100928 B
  cudaFuncSetAttribute(mega_kernel, cudaFuncAttributeMaxDynamicSharedMemorySize, SMEM);

  splitw_kernel<<<32, 256>>>(W1, W2);                                // #1 (resets bars)
  build_kernel<<<NBLK_B, 512>>>(src, dst);                           // #2 zero+hist+scan+scatter
  aggregate_kernel<<<(KNT * 32 + 255) / 256, 256>>>(x_s, x_t, eps);  // #3
  mega_kernel<<<GRID_G, 256, SMEM>>>(b1, g1, be1, b2, g2, be2, out); // #4 (profiled slot)
}